// round 12
// baseline (speedup 1.0000x reference)
#include <cuda_runtime.h>
#include <cuda_bf16.h>
#include <cstdint>

#define NPART 65536
#define NEDGE 524288
#define RIGN  4096

// ---------------- scratch ----------------
constexpr long long O_E1    = 0;
constexpr long long O_E2    = O_E1    + (long long)NEDGE * 128;
constexpr long long O_NODER = O_E2    + (long long)NEDGE * 128;
constexpr long long O_NODES = O_NODER + (long long)NPART * 128;
constexpr long long O_PEH   = O_NODES + (long long)NPART * 128;
constexpr long long O_PE    = O_PEH   + (long long)NPART * 128;
constexpr long long O_PET   = O_PE    + (long long)NPART * 128;
constexpr long long O_EFF   = O_PET   + (long long)NPART * 128;
constexpr long long O_AGG   = O_EFF   + (long long)NPART * 128;
constexpr long long O_POOL  = O_AGG   + (long long)NPART * 128;
constexpr long long O_RIGID = O_POOL  + 128;
constexpr long long O_TOTAL = O_RIGID + 64;

__device__ float g_buf[O_TOTAL];

// ---------------- mma.sync helpers ----------------
__device__ __forceinline__ uint32_t smem_u32(const void* p) {
    uint32_t a;
    asm("{ .reg .u64 t; cvta.to.shared.u64 t, %1; cvt.u32.u64 %0, t; }" : "=r"(a) : "l"(p));
    return a;
}
__device__ __forceinline__ void ldsm4(uint32_t* r, uint32_t addr) {
    asm volatile("ldmatrix.sync.aligned.m8n8.x4.shared.b16 {%0,%1,%2,%3}, [%4];"
        : "=r"(r[0]), "=r"(r[1]), "=r"(r[2]), "=r"(r[3]) : "r"(addr));
}
__device__ __forceinline__ void mma16816(float* c, const uint32_t* a, const uint32_t* b) {
    asm volatile(
        "mma.sync.aligned.m16n8k16.row.col.f32.bf16.bf16.f32 "
        "{%0,%1,%2,%3}, {%4,%5,%6,%7}, {%8,%9}, {%0,%1,%2,%3};"
        : "+f"(c[0]), "+f"(c[1]), "+f"(c[2]), "+f"(c[3])
        : "r"(a[0]), "r"(a[1]), "r"(a[2]), "r"(a[3]), "r"(b[0]), "r"(b[1]));
}
__device__ __forceinline__ void cvt_split(float a, float b, uint32_t& hi, uint32_t& lo) {
    __nv_bfloat162 h = __floats2bfloat162_rn(a, b);
    hi = *(uint32_t*)&h;
    float ra = a - __bfloat162float(h.x);
    float rb = b - __bfloat162float(h.y);
    __nv_bfloat162 l = __floats2bfloat162_rn(ra, rb);
    lo = *(uint32_t*)&l;
}

// byte offset within a 256B-row swizzled tile (16B units XOR row&7)
__device__ __forceinline__ uint32_t sw_off(int row, int unit, int within) {
    return (uint32_t)(row * 256 + (((unit) ^ (row & 7)) << 4) + within);
}

// ---------------- shared fused-MLP machinery (node: 8 warps, 32x32) ----------------
struct MmaCtx {
    uint32_t sb;
    uint32_t baseA0, baseA1, baseB0, baseB1;
    int rxA0, rxA1, rxB0, rxB1, uA0, uB0;
};
__device__ __forceinline__ MmaCtx make_ctx(uint32_t sb, int wm, int wn, int lane) {
    MmaCtx c; c.sb = sb;
    int rowA0 = wm * 32 + (lane & 15), rowA1 = rowA0 + 16;
    c.baseA0 = (uint32_t)(rowA0 * 256); c.baseA1 = (uint32_t)(rowA1 * 256);
    c.rxA0 = rowA0 & 7; c.rxA1 = rowA1 & 7;
    c.uA0 = lane >> 4;
    int rlB = (lane & 7) + ((lane >> 4) << 3);
    c.uB0 = (lane >> 3) & 1;
    int rowB0 = wn * 32 + rlB, rowB1 = rowB0 + 16;
    c.rxB0 = rowB0 & 7; c.rxB1 = rowB1 & 7;
    c.baseB0 = (uint32_t)(rowB0 * 256); c.baseB1 = (uint32_t)(rowB1 * 256);
    return c;
}
__device__ __forceinline__ void mma_layer(const MmaCtx& c, uint32_t actHi, uint32_t actLo,
                                          uint32_t wHi, uint32_t wLo, float acc[2][4][4]) {
#pragma unroll
    for (int mt = 0; mt < 2; mt++)
#pragma unroll
        for (int nt = 0; nt < 4; nt++)
#pragma unroll
            for (int q = 0; q < 4; q++) acc[mt][nt][q] = 0.f;
#pragma unroll
    for (int pass = 0; pass < 3; pass++) {
        uint32_t Ab = c.sb + (pass == 2 ? actLo : actHi);
        uint32_t Bb = c.sb + (pass == 1 ? wLo : wHi);
#pragma unroll
        for (int ks = 0; ks < 8; ks++) {
            uint32_t a0[4], a1[4], f0[4], f1[4];
            ldsm4(a0, Ab + c.baseA0 + ((uint32_t)((ks * 2 + c.uA0) ^ c.rxA0) << 4));
            ldsm4(a1, Ab + c.baseA1 + ((uint32_t)((ks * 2 + c.uA0) ^ c.rxA1) << 4));
            ldsm4(f0, Bb + c.baseB0 + ((uint32_t)((ks * 2 + c.uB0) ^ c.rxB0) << 4));
            ldsm4(f1, Bb + c.baseB1 + ((uint32_t)((ks * 2 + c.uB0) ^ c.rxB1) << 4));
            mma16816(acc[0][0], a0, f0 + 0);
            mma16816(acc[0][1], a0, f0 + 2);
            mma16816(acc[0][2], a0, f1 + 0);
            mma16816(acc[0][3], a0, f1 + 2);
            mma16816(acc[1][0], a1, f0 + 0);
            mma16816(acc[1][1], a1, f0 + 2);
            mma16816(acc[1][2], a1, f1 + 0);
            mma16816(acc[1][3], a1, f1 + 2);
        }
    }
}
// load a 128x128 weight tile (row stride ldw) into hi/lo swizzled tiles
__device__ __forceinline__ void load_weight_tile_n(char* smem, int dstHi, int dstLo,
                                                   const float* W, int ldw, int tid, int nthr) {
    for (int i = tid; i < 4096; i += nthr) {
        int n = i >> 5, k4 = i & 31;
        float4 v = *(const float4*)(W + (long long)n * ldw + k4 * 4);
        uint32_t h0, l0, h1, l1;
        cvt_split(v.x, v.y, h0, l0);
        cvt_split(v.z, v.w, h1, l1);
        uint32_t off = sw_off(n, k4 >> 1, (k4 & 1) * 8);
        *(uint2*)(smem + dstHi + off) = make_uint2(h0, h1);
        *(uint2*)(smem + dstLo + off) = make_uint2(l0, l1);
    }
}
// load a 64x128 fp32 activation tile into hi/lo swizzled tiles (256 threads)
__device__ __forceinline__ void load_act_tile(char* smem, int actHi, int actLo,
                                              const float* src, int tid) {
    const float4* A4 = (const float4*)src;
#pragma unroll
    for (int it = 0; it < 8; it++) {
        int i = tid + it * 256;
        int row = i >> 5, c4 = i & 31;
        float4 v = A4[i];
        uint32_t h0, l0, h1, l1;
        cvt_split(v.x, v.y, h0, l0);
        cvt_split(v.z, v.w, h1, l1);
        uint32_t off = sw_off(row, c4 >> 1, (c4 & 1) * 8);
        *(uint2*)(smem + actHi + off) = make_uint2(h0, h1);
        *(uint2*)(smem + actLo + off) = make_uint2(l0, l1);
    }
}
// relu(acc + bias) -> activation tile writeback (node 8-warp shape)
__device__ __forceinline__ void store_act_relu(char* smem, int actHi, int actLo,
                                               int wm, int wn, int qr, int qc,
                                               float acc[2][4][4], const float* bias) {
#pragma unroll
    for (int mt = 0; mt < 2; mt++) {
        int row0 = wm * 32 + mt * 16 + qr;
        int row1 = row0 + 8;
#pragma unroll
        for (int nt = 0; nt < 4; nt++) {
            int col = wn * 32 + nt * 8 + qc;
            float bx = bias ? bias[col] : 0.f, by = bias ? bias[col + 1] : 0.f;
            float o0 = fmaxf(acc[mt][nt][0] + bx, 0.f);
            float o1 = fmaxf(acc[mt][nt][1] + by, 0.f);
            float o2 = fmaxf(acc[mt][nt][2] + bx, 0.f);
            float o3 = fmaxf(acc[mt][nt][3] + by, 0.f);
            uint32_t h0, l0, h1, l1;
            cvt_split(o0, o1, h0, l0);
            cvt_split(o2, o3, h1, l1);
            uint32_t offA = sw_off(row0, col >> 3, (col & 7) * 2);
            uint32_t offB = sw_off(row1, col >> 3, (col & 7) * 2);
            *(uint32_t*)(smem + actHi + offA) = h0;
            *(uint32_t*)(smem + actLo + offA) = l0;
            *(uint32_t*)(smem + actHi + offB) = h1;
            *(uint32_t*)(smem + actLo + offB) = l1;
        }
    }
}

// ---------------- smem layout ----------------
#define FE_W(L, h)  ((L) * 65536 + (h) * 32768)
#define FE_SA_HI    196608
#define FE_SA_LO    212992
#define FE_CONST    229376
#define FE_SMEM     231936
#define ND_SMEM     232192
#define FE_GRID     148
#define FE_TILES    (NEDGE / 64)
#define ND_TILES    (NPART / 64)
#define RIG_TILES   (RIGN / 64)

// ================= fused edge pipeline (4 warps, 32x64 warp tiles) =================
__global__ void __launch_bounds__(128, 1) k_edge_fused(
    const float* __restrict__ nodeR, const float* __restrict__ nodeS,
    const float* __restrict__ Ra, const int* __restrict__ recv, const int* __restrict__ send,
    const float* __restrict__ re_w0, const float* __restrict__ re_b0,
    const float* __restrict__ W1, const float* __restrict__ b1,
    const float* __restrict__ W2, const float* __restrict__ b2,
    const float* __restrict__ W3, const float* __restrict__ b3,
    float* __restrict__ Z, float* __restrict__ agg)
{
    extern __shared__ char smem[];
    uint32_t sb = smem_u32(smem);
    int tid = threadIdx.x;
    int lane = tid & 31, wid = tid >> 5;
    int wm = wid >> 1;          // 2 m-groups of 32 rows
    int wn = wid & 1;           // 2 n-groups of 64 cols
    int qr = lane >> 2, qc = (lane & 3) * 2;

    float* cwra = (float*)(smem + FE_CONST);
    float* cb0  = cwra + 128;
    float* cbl[3] = {cb0 + 128, cb0 + 256, cb0 + 384};

    {
        const float* Ws[3] = {W1, W2, W3};
        const int ldws[3] = {128, 128, 384};
#pragma unroll
        for (int L = 0; L < 3; L++)
            load_weight_tile_n(smem, FE_W(L, 0), FE_W(L, 1), Ws[L], ldws[L], tid, 128);
        if (tid < 128) {
            cwra[tid] = re_w0[tid * 31 + 30];
            cb0[tid]  = re_b0[tid];
            cbl[0][tid] = b1[tid];
            cbl[1][tid] = b2[tid];
            cbl[2][tid] = b3[tid];
        }
    }
    __syncthreads();

    // mma lane addressing: A rows wm*32..+31 (two m16), B rows wn*64..+63 (four n16 groups)
    int rowA0 = wm * 32 + (lane & 15), rowA1 = rowA0 + 16;
    uint32_t baseA0 = (uint32_t)(rowA0 * 256), baseA1 = (uint32_t)(rowA1 * 256);
    int rxA0 = rowA0 & 7, rxA1 = rowA1 & 7;
    int uA0 = lane >> 4;
    int rlB = (lane & 7) + ((lane >> 4) << 3);
    int uB0 = (lane >> 3) & 1;
    uint32_t baseB[4]; int rxB[4];
#pragma unroll
    for (int p = 0; p < 4; p++) {
        int rowB = wn * 64 + p * 16 + rlB;
        baseB[p] = (uint32_t)(rowB * 256);
        rxB[p] = rowB & 7;
    }

    int e_loc = tid >> 1;      // 64 edges, 2 threads each
    int c2 = tid & 1;          // half-row (16 float4s)

    for (int t = blockIdx.x; t < FE_TILES; t += FE_GRID) {
        long long ebase = (long long)t * 64;

        // ---- gather h0 tile (direct; L2-resident node tables) ----
        {
            long long eg = ebase + e_loc;
            int r = recv[eg], s = send[eg];
            float ra = Ra[eg];
            const float4* nr = (const float4*)(nodeR + (long long)r * 128);
            const float4* ns = (const float4*)(nodeS + (long long)s * 128);
#pragma unroll
            for (int i = 0; i < 16; i++) {
                int c4 = c2 * 16 + i;
                int col = c4 * 4;
                float4 a = nr[c4];
                float4 b = ns[c4];
                float v0 = fmaxf(a.x + b.x + ra * cwra[col + 0] + cb0[col + 0], 0.f);
                float v1 = fmaxf(a.y + b.y + ra * cwra[col + 1] + cb0[col + 1], 0.f);
                float v2 = fmaxf(a.z + b.z + ra * cwra[col + 2] + cb0[col + 2], 0.f);
                float v3 = fmaxf(a.w + b.w + ra * cwra[col + 3] + cb0[col + 3], 0.f);
                uint32_t h0, l0, h1, l1;
                cvt_split(v0, v1, h0, l0);
                cvt_split(v2, v3, h1, l1);
                uint32_t off = sw_off(e_loc, c4 >> 1, (c4 & 1) * 8);
                *(uint2*)(smem + FE_SA_HI + off) = make_uint2(h0, h1);
                *(uint2*)(smem + FE_SA_LO + off) = make_uint2(l0, l1);
            }
        }
        __syncthreads();

#pragma unroll
        for (int L = 0; L < 3; L++) {
            float acc[2][8][4];
#pragma unroll
            for (int mt = 0; mt < 2; mt++)
#pragma unroll
                for (int nt = 0; nt < 8; nt++)
#pragma unroll
                    for (int q = 0; q < 4; q++) acc[mt][nt][q] = 0.f;

#pragma unroll
            for (int pass = 0; pass < 3; pass++) {
                uint32_t Ab = sb + (pass == 2 ? FE_SA_LO : FE_SA_HI);
                uint32_t Bb = sb + FE_W(L, pass == 1 ? 1 : 0);
#pragma unroll
                for (int ks = 0; ks < 8; ks++) {
                    uint32_t a0[4], a1[4], f[4][4];
                    ldsm4(a0, Ab + baseA0 + ((uint32_t)((ks * 2 + uA0) ^ rxA0) << 4));
                    ldsm4(a1, Ab + baseA1 + ((uint32_t)((ks * 2 + uA0) ^ rxA1) << 4));
#pragma unroll
                    for (int p = 0; p < 4; p++)
                        ldsm4(f[p], Bb + baseB[p] + ((uint32_t)((ks * 2 + uB0) ^ rxB[p]) << 4));
#pragma unroll
                    for (int p = 0; p < 4; p++) {
                        mma16816(acc[0][p * 2 + 0], a0, f[p] + 0);
                        mma16816(acc[0][p * 2 + 1], a0, f[p] + 2);
                        mma16816(acc[1][p * 2 + 0], a1, f[p] + 0);
                        mma16816(acc[1][p * 2 + 1], a1, f[p] + 2);
                    }
                }
            }
            __syncthreads();

            if (L < 2) {
#pragma unroll
                for (int mt = 0; mt < 2; mt++) {
                    int row0 = wm * 32 + mt * 16 + qr;
                    int row1 = row0 + 8;
#pragma unroll
                    for (int nt = 0; nt < 8; nt++) {
                        int col = wn * 64 + nt * 8 + qc;
                        float bx = cbl[L][col], by = cbl[L][col + 1];
                        float o0 = fmaxf(acc[mt][nt][0] + bx, 0.f);
                        float o1 = fmaxf(acc[mt][nt][1] + by, 0.f);
                        float o2 = fmaxf(acc[mt][nt][2] + bx, 0.f);
                        float o3 = fmaxf(acc[mt][nt][3] + by, 0.f);
                        uint32_t h0, l0, h1, l1;
                        cvt_split(o0, o1, h0, l0);
                        cvt_split(o2, o3, h1, l1);
                        uint32_t offA = sw_off(row0, col >> 3, (col & 7) * 2);
                        uint32_t offB = sw_off(row1, col >> 3, (col & 7) * 2);
                        *(uint32_t*)(smem + FE_SA_HI + offA) = h0;
                        *(uint32_t*)(smem + FE_SA_LO + offA) = l0;
                        *(uint32_t*)(smem + FE_SA_HI + offB) = h1;
                        *(uint32_t*)(smem + FE_SA_LO + offB) = l1;
                    }
                }
                __syncthreads();
            } else {
                // Z store + fused step-1 scatter
#pragma unroll
                for (int mt = 0; mt < 2; mt++) {
                    long long e0 = ebase + wm * 32 + mt * 16 + qr;
                    int rA = recv[e0], rB = recv[e0 + 8];
#pragma unroll
                    for (int nt = 0; nt < 8; nt++) {
                        int col = wn * 64 + nt * 8 + qc;
                        float bx = cbl[2][col], by = cbl[2][col + 1];
                        float o0 = acc[mt][nt][0] + bx, o1 = acc[mt][nt][1] + by;
                        float o2 = acc[mt][nt][2] + bx, o3 = acc[mt][nt][3] + by;
                        *(float2*)(Z + e0 * 128 + col)       = make_float2(o0, o1);
                        *(float2*)(Z + (e0 + 8) * 128 + col) = make_float2(o2, o3);
                        atomicAdd(&agg[(long long)rA * 128 + col],     fmaxf(o0, 0.f));
                        atomicAdd(&agg[(long long)rA * 128 + col + 1], fmaxf(o1, 0.f));
                        atomicAdd(&agg[(long long)rB * 128 + col],     fmaxf(o2, 0.f));
                        atomicAdd(&agg[(long long)rB * 128 + col + 1], fmaxf(o3, 0.f));
                    }
                }
            }
        }
    }
}

// ================= fused node prep: pet = relu(peh@pe_w1+pe_b1)@pp_w1 + pp_b (+zero agg) =====
__global__ void __launch_bounds__(256, 1) k_node_prep(
    const float* __restrict__ peh,
    const float* __restrict__ pe_w1, const float* __restrict__ pe_b1,
    const float* __restrict__ pp_w, const float* __restrict__ pp_b,
    float* __restrict__ pet, float* __restrict__ agg)
{
    extern __shared__ char smem[];
    uint32_t sb = smem_u32(smem);
    int tid = threadIdx.x;
    int lane = tid & 31, wid = tid >> 5;
    int wm = wid >> 2, wn = wid & 3;
    int qr = lane >> 2, qc = (lane & 3) * 2;

    // zero agg (+pooled) for the edge scatter that follows
    {
        long long total = (long long)NPART * 128 + 128;
        float4 z4 = make_float4(0.f, 0.f, 0.f, 0.f);
        for (long long i = ((long long)blockIdx.x * 256 + tid) * 4; i + 3 < total;
             i += (long long)FE_GRID * 256 * 4)
            *(float4*)(agg + i) = z4;
        if (blockIdx.x == 0 && tid < 128) agg[(long long)NPART * 128 + tid] = 0.f;
    }

    float* cb = (float*)(smem + FE_CONST);
    load_weight_tile_n(smem, FE_W(0, 0), FE_W(0, 1), pe_w1, 128, tid, 256);
    load_weight_tile_n(smem, FE_W(1, 0), FE_W(1, 1), pp_w, 256, tid, 256);
    if (tid < 128) { cb[tid] = pe_b1[tid]; cb[128 + tid] = pp_b[tid]; }
    __syncthreads();

    MmaCtx ctx = make_ctx(sb, wm, wn, lane);

    for (int t = blockIdx.x; t < ND_TILES; t += FE_GRID) {
        load_act_tile(smem, FE_SA_HI, FE_SA_LO, peh + (long long)t * 64 * 128, tid);
        __syncthreads();

        float acc[2][4][4];
        mma_layer(ctx, FE_SA_HI, FE_SA_LO, FE_W(0, 0), FE_W(0, 1), acc);
        __syncthreads();
        store_act_relu(smem, FE_SA_HI, FE_SA_LO, wm, wn, qr, qc, acc, cb);
        __syncthreads();
        mma_layer(ctx, FE_SA_HI, FE_SA_LO, FE_W(1, 0), FE_W(1, 1), acc);
        __syncthreads();
#pragma unroll
        for (int mt = 0; mt < 2; mt++) {
            long long r0 = (long long)t * 64 + wm * 32 + mt * 16 + qr;
#pragma unroll
            for (int nt = 0; nt < 4; nt++) {
                int col = wn * 32 + nt * 8 + qc;
                float bx = cb[128 + col], by = cb[128 + col + 1];
                *(float2*)(pet + r0 * 128 + col)       = make_float2(acc[mt][nt][0] + bx, acc[mt][nt][1] + by);
                *(float2*)(pet + (r0 + 8) * 128 + col) = make_float2(acc[mt][nt][2] + bx, acc[mt][nt][3] + by);
            }
        }
    }
}

// ================= fused step-1 update + U/V (also re-zeroes agg + pooled) =================
__global__ void __launch_bounds__(256, 1) k_node_step1uv(
    float* __restrict__ agg, const float* __restrict__ pet,
    const float* __restrict__ pp_w, const float* __restrict__ rp_w,
    float* __restrict__ U, float* __restrict__ V, float* __restrict__ pooled)
{
    extern __shared__ char smem[];
    uint32_t sb = smem_u32(smem);
    int tid = threadIdx.x;
    int lane = tid & 31, wid = tid >> 5;
    int wm = wid >> 2, wn = wid & 3;
    int qr = lane >> 2, qc = (lane & 3) * 2;

    if (blockIdx.x == 0 && tid < 128) pooled[tid] = 0.f;

    load_weight_tile_n(smem, FE_W(0, 0), FE_W(0, 1), pp_w + 128, 256, tid, 256);
    load_weight_tile_n(smem, FE_W(1, 0), FE_W(1, 1), rp_w + 128, 384, tid, 256);
    load_weight_tile_n(smem, FE_W(2, 0), FE_W(2, 1), rp_w + 256, 384, tid, 256);
    __syncthreads();

    MmaCtx ctx = make_ctx(sb, wm, wn, lane);

    for (int t = blockIdx.x; t < ND_TILES; t += FE_GRID) {
        // load agg tile into act; zero it behind us (each element touched once)
        {
            float4* A4 = (float4*)(agg + (long long)t * 64 * 128);
            float4 z4 = make_float4(0.f, 0.f, 0.f, 0.f);
#pragma unroll
            for (int it = 0; it < 8; it++) {
                int i = tid + it * 256;
                int row = i >> 5, c4 = i & 31;
                float4 v = A4[i];
                A4[i] = z4;
                uint32_t h0, l0, h1, l1;
                cvt_split(v.x, v.y, h0, l0);
                cvt_split(v.z, v.w, h1, l1);
                uint32_t off = sw_off(row, c4 >> 1, (c4 & 1) * 8);
                *(uint2*)(smem + FE_SA_HI + off) = make_uint2(h0, h1);
                *(uint2*)(smem + FE_SA_LO + off) = make_uint2(l0, l1);
            }
        }
        __syncthreads();

        float acc[2][4][4];
        mma_layer(ctx, FE_SA_HI, FE_SA_LO, FE_W(0, 0), FE_W(0, 1), acc);
        __syncthreads();
#pragma unroll
        for (int mt = 0; mt < 2; mt++) {
            long long r0 = (long long)t * 64 + wm * 32 + mt * 16 + qr;
#pragma unroll
            for (int nt = 0; nt < 4; nt++) {
                int col = wn * 32 + nt * 8 + qc;
                float2 d0 = *(const float2*)(pet + r0 * 128 + col);
                float2 d1 = *(const float2*)(pet + (r0 + 8) * 128 + col);
                acc[mt][nt][0] += d0.x; acc[mt][nt][1] += d0.y;
                acc[mt][nt][2] += d1.x; acc[mt][nt][3] += d1.y;
            }
        }
        store_act_relu(smem, FE_SA_HI, FE_SA_LO, wm, wn, qr, qc, acc, nullptr);
        __syncthreads();

        mma_layer(ctx, FE_SA_HI, FE_SA_LO, FE_W(1, 0), FE_W(1, 1), acc);
#pragma unroll
        for (int mt = 0; mt < 2; mt++) {
            long long r0 = (long long)t * 64 + wm * 32 + mt * 16 + qr;
#pragma unroll
            for (int nt = 0; nt < 4; nt++) {
                int col = wn * 32 + nt * 8 + qc;
                *(float2*)(U + r0 * 128 + col)       = make_float2(acc[mt][nt][0], acc[mt][nt][1]);
                *(float2*)(U + (r0 + 8) * 128 + col) = make_float2(acc[mt][nt][2], acc[mt][nt][3]);
            }
        }
        mma_layer(ctx, FE_SA_HI, FE_SA_LO, FE_W(2, 0), FE_W(2, 1), acc);
        __syncthreads();
#pragma unroll
        for (int mt = 0; mt < 2; mt++) {
            long long r0 = (long long)t * 64 + wm * 32 + mt * 16 + qr;
#pragma unroll
            for (int nt = 0; nt < 4; nt++) {
                int col = wn * 32 + nt * 8 + qc;
                *(float2*)(V + r0 * 128 + col)       = make_float2(acc[mt][nt][0], acc[mt][nt][1]);
                *(float2*)(V + (r0 + 8) * 128 + col) = make_float2(acc[mt][nt][2], acc[mt][nt][3]);
            }
        }
    }
}

// ================= fused step-2 update + rigid pool + fluid MLP + out =================
__global__ void __launch_bounds__(256, 1) k_node_step2(
    const float* __restrict__ agg, const float* __restrict__ pet,
    const float* __restrict__ pp_w,
    const float* __restrict__ fl_w0, const float* __restrict__ fl_b0,
    const float* __restrict__ fl_w1, const float* __restrict__ fl_b1,
    const float* __restrict__ fl_w2, const float* __restrict__ fl_b2,
    float* __restrict__ pooled, float* __restrict__ out)
{
    extern __shared__ char smem[];
    uint32_t sb = smem_u32(smem);
    int tid = threadIdx.x;
    int lane = tid & 31, wid = tid >> 5;
    int wm = wid >> 2, wn = wid & 3;
    int qr = lane >> 2, qc = (lane & 3) * 2;

    float* cb0 = (float*)(smem + FE_CONST);
    float* cb1 = cb0 + 128;
    float* cw2 = cb1 + 128;
    float* cb2 = cw2 + 384;

    load_weight_tile_n(smem, FE_W(0, 0), FE_W(0, 1), pp_w + 128, 256, tid, 256);
    load_weight_tile_n(smem, FE_W(1, 0), FE_W(1, 1), fl_w0, 128, tid, 256);
    load_weight_tile_n(smem, FE_W(2, 0), FE_W(2, 1), fl_w1, 128, tid, 256);
    if (tid < 128) { cb0[tid] = fl_b0[tid]; cb1[tid] = fl_b1[tid]; }
    if (tid < 128) { cw2[tid] = fl_w2[tid]; cw2[128 + tid] = fl_w2[128 + tid]; cw2[256 + tid] = fl_w2[256 + tid]; }
    if (tid < 3) cb2[tid] = fl_b2[tid];
    __syncthreads();

    MmaCtx ctx = make_ctx(sb, wm, wn, lane);

    for (int t = blockIdx.x; t < ND_TILES; t += FE_GRID) {
        load_act_tile(smem, FE_SA_HI, FE_SA_LO, agg + (long long)t * 64 * 128, tid);
        __syncthreads();

        float acc[2][4][4];
        mma_layer(ctx, FE_SA_HI, FE_SA_LO, FE_W(0, 0), FE_W(0, 1), acc);
        __syncthreads();
#pragma unroll
        for (int mt = 0; mt < 2; mt++) {
            long long r0 = (long long)t * 64 + wm * 32 + mt * 16 + qr;
#pragma unroll
            for (int nt = 0; nt < 4; nt++) {
                int col = wn * 32 + nt * 8 + qc;
                float2 d0 = *(const float2*)(pet + r0 * 128 + col);
                float2 d1 = *(const float2*)(pet + (r0 + 8) * 128 + col);
                acc[mt][nt][0] = fmaxf(acc[mt][nt][0] + d0.x, 0.f);
                acc[mt][nt][1] = fmaxf(acc[mt][nt][1] + d0.y, 0.f);
                acc[mt][nt][2] = fmaxf(acc[mt][nt][2] + d1.x, 0.f);
                acc[mt][nt][3] = fmaxf(acc[mt][nt][3] + d1.y, 0.f);
            }
        }

        if (t < RIG_TILES) {
            float pl[4][2];
#pragma unroll
            for (int nt = 0; nt < 4; nt++) {
                pl[nt][0] = acc[0][nt][0] + acc[0][nt][2] + acc[1][nt][0] + acc[1][nt][2];
                pl[nt][1] = acc[0][nt][1] + acc[0][nt][3] + acc[1][nt][1] + acc[1][nt][3];
            }
#pragma unroll
            for (int nt = 0; nt < 4; nt++) {
                int col = wn * 32 + nt * 8 + qc;
                atomicAdd(&pooled[col],     pl[nt][0]);
                atomicAdd(&pooled[col + 1], pl[nt][1]);
            }
            continue;
        }

#pragma unroll
        for (int mt = 0; mt < 2; mt++) {
            int row0 = wm * 32 + mt * 16 + qr;
            int row1 = row0 + 8;
#pragma unroll
            for (int nt = 0; nt < 4; nt++) {
                int col = wn * 32 + nt * 8 + qc;
                uint32_t h0, l0, h1, l1;
                cvt_split(acc[mt][nt][0], acc[mt][nt][1], h0, l0);
                cvt_split(acc[mt][nt][2], acc[mt][nt][3], h1, l1);
                uint32_t offA = sw_off(row0, col >> 3, (col & 7) * 2);
                uint32_t offB = sw_off(row1, col >> 3, (col & 7) * 2);
                *(uint32_t*)(smem + FE_SA_HI + offA) = h0;
                *(uint32_t*)(smem + FE_SA_LO + offA) = l0;
                *(uint32_t*)(smem + FE_SA_HI + offB) = h1;
                *(uint32_t*)(smem + FE_SA_LO + offB) = l1;
            }
        }
        __syncthreads();

        mma_layer(ctx, FE_SA_HI, FE_SA_LO, FE_W(1, 0), FE_W(1, 1), acc);
        __syncthreads();
        store_act_relu(smem, FE_SA_HI, FE_SA_LO, wm, wn, qr, qc, acc, cb0);
        __syncthreads();
        mma_layer(ctx, FE_SA_HI, FE_SA_LO, FE_W(2, 0), FE_W(2, 1), acc);
        __syncthreads();
        store_act_relu(smem, FE_SA_HI, FE_SA_LO, wm, wn, qr, qc, acc, cb1);
        __syncthreads();

        {
            int row = tid >> 2;
            int q = tid & 3;
            long long g = (long long)t * 64 + row;
            float s0 = 0.f, s1 = 0.f, s2 = 0.f;
#pragma unroll
            for (int j = q * 16; j < q * 16 + 16; j++) {
                uint32_t off = sw_off(row, j >> 2, (j * 4) & 15);
                uint32_t h = *(uint32_t*)(smem + FE_SA_HI + off);
                uint32_t l = *(uint32_t*)(smem + FE_SA_LO + off);
                __nv_bfloat162 hb = *(__nv_bfloat162*)&h;
                __nv_bfloat162 lb = *(__nv_bfloat162*)&l;
                float f0 = __bfloat162float(hb.x) + __bfloat162float(lb.x);
                float f1 = __bfloat162float(hb.y) + __bfloat162float(lb.y);
                int c = 2 * j;
                s0 += f0 * cw2[c] + f1 * cw2[c + 1];
                s1 += f0 * cw2[128 + c] + f1 * cw2[128 + c + 1];
                s2 += f0 * cw2[256 + c] + f1 * cw2[256 + c + 1];
            }
            s0 += __shfl_xor_sync(0xffffffffu, s0, 1); s0 += __shfl_xor_sync(0xffffffffu, s0, 2);
            s1 += __shfl_xor_sync(0xffffffffu, s1, 1); s1 += __shfl_xor_sync(0xffffffffu, s1, 2);
            s2 += __shfl_xor_sync(0xffffffffu, s2, 1); s2 += __shfl_xor_sync(0xffffffffu, s2, 2);
            if (q == 0) {
                out[g * 3 + 0] = s0 + cb2[0];
                out[g * 3 + 1] = s1 + cb2[1];
                out[g * 3 + 2] = s2 + cb2[2];
            }
        }
        __syncthreads();
    }
}

// ---------------- utility ----------------
__global__ void k_centroid(const float* __restrict__ state, float* __restrict__ cent) {
    float acc[6] = {0, 0, 0, 0, 0, 0};
    for (int i = threadIdx.x; i < RIGN; i += blockDim.x) {
        const float* s = state + i * 6;
#pragma unroll
        for (int c = 0; c < 6; c++) acc[c] += s[c];
    }
    __shared__ float cs[6];
    if (threadIdx.x < 6) cs[threadIdx.x] = 0.f;
    __syncthreads();
#pragma unroll
    for (int c = 0; c < 6; c++) atomicAdd(&cs[c], acc[c]);
    __syncthreads();
    if (threadIdx.x < 6) cent[threadIdx.x] = cs[threadIdx.x] * (1.f / RIGN);
}

// ---------------- node preprocessing ----------------
#define NPB 16
__global__ void __launch_bounds__(128) k_node_pre(
    const float* __restrict__ attr, const float* __restrict__ state,
    const float* __restrict__ pe_w0, const float* __restrict__ pe_b0,
    const float* __restrict__ re_w0, const float* __restrict__ cent,
    float* __restrict__ peh, float* __restrict__ nodeR, float* __restrict__ nodeS)
{
    int tid = threadIdx.x;
    float rpe[15], rR[15], rS[15];
#pragma unroll
    for (int k = 0; k < 15; k++) rpe[k] = pe_w0[tid * 15 + k];
#pragma unroll
    for (int k = 0; k < 9; k++) { rR[k] = re_w0[tid * 31 + k]; rS[k] = re_w0[tid * 31 + 9 + k]; }
#pragma unroll
    for (int k = 0; k < 6; k++) { rR[9 + k] = re_w0[tid * 31 + 18 + k]; rS[9 + k] = re_w0[tid * 31 + 24 + k]; }
    float bpe = pe_b0[tid];
    float c6[6];
#pragma unroll
    for (int c = 0; c < 6; c++) c6[c] = cent[c];

    __shared__ float xin[NPB][9];
    int base = blockIdx.x * NPB;
    for (int j = tid; j < NPB * 9; j += 128) {
        int nd = j / 9, c = j % 9;
        xin[nd][c] = (c < 3) ? attr[(base + nd) * 3 + c] : state[(base + nd) * 6 + (c - 3)];
    }
    __syncthreads();
    for (int nd = 0; nd < NPB; nd++) {
        int g = base + nd;
        float in[15], st[6];
        in[0] = xin[nd][0]; in[1] = xin[nd][1]; in[2] = xin[nd][2];
#pragma unroll
        for (int c = 0; c < 6; c++) {
            st[c] = xin[nd][3 + c];
            in[3 + c] = (g < RIGN) ? (st[c] - c6[c]) : 0.f;
            in[9 + c] = st[c];
        }
        float a0 = bpe, a1 = 0.f, a2 = 0.f;
#pragma unroll
        for (int k = 0; k < 15; k++) a0 = fmaf(in[k], rpe[k], a0);
#pragma unroll
        for (int k = 0; k < 9; k++) { a1 = fmaf(in[k], rR[k], a1); a2 = fmaf(in[k], rS[k], a2); }
#pragma unroll
        for (int k = 0; k < 6; k++) { a1 = fmaf(st[k], rR[9 + k], a1); a2 = fmaf(st[k], rS[9 + k], a2); }
        peh[g * 128 + tid]   = fmaxf(a0, 0.f);
        nodeR[g * 128 + tid] = a1;
        nodeS[g * 128 + tid] = a2;
    }
}

// ---------------- step-2 edge propagation (8 ch/thread) ----------------
__global__ void __launch_bounds__(256) k_edge_prop(
    const float* __restrict__ Z, const float* __restrict__ U, const float* __restrict__ V,
    const int* __restrict__ recv, const int* __restrict__ send,
    float* __restrict__ agg)
{
    long long idx = (long long)blockIdx.x * 256 + threadIdx.x;   // E*16 slots
    int e = (int)(idx >> 4), n8 = (int)(idx & 15) * 8;
    int r = recv[e], s = send[e];
    float4 z0 = *(const float4*)(Z + (long long)e * 128 + n8);
    float4 z1 = *(const float4*)(Z + (long long)e * 128 + n8 + 4);
    float4 u0 = *(const float4*)(U + (long long)r * 128 + n8);
    float4 u1 = *(const float4*)(U + (long long)r * 128 + n8 + 4);
    float4 v0 = *(const float4*)(V + (long long)s * 128 + n8);
    float4 v1 = *(const float4*)(V + (long long)s * 128 + n8 + 4);
    float* a = agg + (long long)r * 128 + n8;
    atomicAdd(a + 0, fmaxf(z0.x + u0.x + v0.x, 0.f));
    atomicAdd(a + 1, fmaxf(z0.y + u0.y + v0.y, 0.f));
    atomicAdd(a + 2, fmaxf(z0.z + u0.z + v0.z, 0.f));
    atomicAdd(a + 3, fmaxf(z0.w + u0.w + v0.w, 0.f));
    atomicAdd(a + 4, fmaxf(z1.x + u1.x + v1.x, 0.f));
    atomicAdd(a + 5, fmaxf(z1.y + u1.y + v1.y, 0.f));
    atomicAdd(a + 6, fmaxf(z1.z + u1.z + v1.z, 0.f));
    atomicAdd(a + 7, fmaxf(z1.w + u1.w + v1.w, 0.f));
}

// ---------------- rigid branch ----------------
__global__ void __launch_bounds__(128) k_rigid(
    const float* __restrict__ state, const float* __restrict__ pooled,
    const float* __restrict__ w0, const float* __restrict__ b0,
    const float* __restrict__ w1, const float* __restrict__ b1,
    const float* __restrict__ w2, const float* __restrict__ b2,
    const float* __restrict__ cent, float* __restrict__ out)
{
    int tid = threadIdx.x;
    __shared__ float s0[128], s1[128], s2[128], t[7], Rm[9], bb[3], cc[3];
    s0[tid] = pooled[tid] * (1.f / RIGN);
    __syncthreads();
    float a = b0[tid];
    for (int k = 0; k < 128; k++) a = fmaf(s0[k], w0[tid * 128 + k], a);
    s1[tid] = fmaxf(a, 0.f);
    __syncthreads();
    a = b1[tid];
    for (int k = 0; k < 128; k++) a = fmaf(s1[k], w1[tid * 128 + k], a);
    s2[tid] = fmaxf(a, 0.f);
    __syncthreads();
    if (tid < 7) {
        a = b2[tid];
        for (int k = 0; k < 128; k++) a = fmaf(s2[k], w2[tid * 128 + k], a);
        t[tid] = a;
    }
    __syncthreads();
    if (tid == 0) {
        float qn = 1.f / sqrtf(t[0]*t[0] + t[1]*t[1] + t[2]*t[2] + t[3]*t[3]);
        float w = t[0]*qn, x = t[1]*qn, y = t[2]*qn, z = t[3]*qn;
        Rm[0] = 1.f - 2.f*(y*y + z*z); Rm[1] = 2.f*(x*y + z*w);       Rm[2] = 2.f*(x*z - y*w);
        Rm[3] = 2.f*(x*y - z*w);       Rm[4] = 1.f - 2.f*(x*x + z*z); Rm[5] = 2.f*(y*z + x*w);
        Rm[6] = 2.f*(x*z + y*w);       Rm[7] = 2.f*(y*z - x*w);       Rm[8] = 1.f - 2.f*(x*x + y*y);
        bb[0] = t[4]; bb[1] = t[5]; bb[2] = t[6];
        cc[0] = cent[0]; cc[1] = cent[1]; cc[2] = cent[2];
    }
    __syncthreads();
    for (int i = tid; i < RIGN; i += 128) {
        float p0x = state[i*6+0], p0y = state[i*6+1], p0z = state[i*6+2];
        float dx = p0x - cc[0], dy = p0y - cc[1], dz = p0z - cc[2];
        float p1x = dx*Rm[0] + dy*Rm[3] + dz*Rm[6] + bb[0] + cc[0];
        float p1y = dx*Rm[1] + dy*Rm[4] + dz*Rm[7] + bb[1] + cc[1];
        float p1z = dx*Rm[2] + dy*Rm[5] + dz*Rm[8] + bb[2] + cc[2];
        out[i*3+0] = (p1x - p0x) * 60.f;
        out[i*3+1] = (p1y - p0y) * 60.f;
        out[i*3+2] = (p1z - p0z) * 60.f;
    }
}

// ---------------- launch ----------------
extern "C" void kernel_launch(void* const* d_in, const int* in_sizes, int n_in,
                              void* d_out, int out_size)
{
    const float* state = (const float*)d_in[0];
    const float* attr  = (const float*)d_in[1];
    const float* Ra    = (const float*)d_in[2];
    const int*   recv  = (const int*)d_in[3];
    const int*   send  = (const int*)d_in[4];
    const float* pe_w0 = (const float*)d_in[5],  *pe_b0 = (const float*)d_in[6];
    const float* pe_w1 = (const float*)d_in[7],  *pe_b1 = (const float*)d_in[8];
    const float* re_w0 = (const float*)d_in[9],  *re_b0 = (const float*)d_in[10];
    const float* re_w1 = (const float*)d_in[11], *re_b1 = (const float*)d_in[12];
    const float* re_w2 = (const float*)d_in[13], *re_b2 = (const float*)d_in[14];
    const float* rp_w  = (const float*)d_in[15], *rp_b  = (const float*)d_in[16];
    const float* pp_w  = (const float*)d_in[17], *pp_b  = (const float*)d_in[18];
    const float* rg_w0 = (const float*)d_in[19], *rg_b0 = (const float*)d_in[20];
    const float* rg_w1 = (const float*)d_in[21], *rg_b1 = (const float*)d_in[22];
    const float* rg_w2 = (const float*)d_in[23], *rg_b2 = (const float*)d_in[24];
    const float* fl_w0 = (const float*)d_in[25], *fl_b0 = (const float*)d_in[26];
    const float* fl_w1 = (const float*)d_in[27], *fl_b1 = (const float*)d_in[28];
    const float* fl_w2 = (const float*)d_in[29], *fl_b2 = (const float*)d_in[30];
    float* out = (float*)d_out;

    static int smem_set = 0;
    if (!smem_set) {
        cudaFuncSetAttribute(k_edge_fused,   cudaFuncAttributeMaxDynamicSharedMemorySize, FE_SMEM);
        cudaFuncSetAttribute(k_node_prep,    cudaFuncAttributeMaxDynamicSharedMemorySize, ND_SMEM);
        cudaFuncSetAttribute(k_node_step1uv, cudaFuncAttributeMaxDynamicSharedMemorySize, ND_SMEM);
        cudaFuncSetAttribute(k_node_step2,   cudaFuncAttributeMaxDynamicSharedMemorySize, ND_SMEM);
        smem_set = 1;
    }

    void* bp = nullptr;
    cudaGetSymbolAddress(&bp, g_buf);
    float* B     = (float*)bp;
    float* E2    = B + O_E2;      // Z
    float* nodeR = B + O_NODER;   // reused as U
    float* nodeS = B + O_NODES;   // reused as V
    float* peh   = B + O_PEH;
    float* pet   = B + O_PET;
    float* agg   = B + O_AGG;
    float* pooled= B + O_POOL;
    float* cent  = B + O_RIGID;

    const int PG = (NEDGE * 16) / 256;

    // prep (k_node_prep also zeroes agg+pooled for the step-1 scatter)
    k_centroid<<<1, 256>>>(state, cent);
    k_node_pre<<<NPART / NPB, 128>>>(attr, state, pe_w0, pe_b0, re_w0, cent,
                                     peh, nodeR, nodeS);
    k_node_prep<<<FE_GRID, 256, ND_SMEM>>>(peh, pe_w1, pe_b1, pp_w, pp_b, pet, agg);

    // fused edge pipeline: h0 -> re1 -> re2 -> Z (+ step-1 scatter into agg)
    k_edge_fused<<<FE_GRID, 128, FE_SMEM>>>(nodeR, nodeS, Ra, recv, send,
                                            re_w0, re_b0,
                                            re_w1, re_b1, re_w2, re_b2,
                                            rp_w, rp_b, E2, agg);

    // step-1 particle update + U/V (consumes agg and re-zeroes it; zeroes pooled)
    k_node_step1uv<<<FE_GRID, 256, ND_SMEM>>>(agg, pet, pp_w, rp_w, nodeR, nodeS, pooled);

    // step-2 propagation
    k_edge_prop<<<PG, 256>>>(E2, nodeR, nodeS, recv, send, agg);

    // step-2 particle update + rigid pooling + fluid MLP + fluid output
    k_node_step2<<<FE_GRID, 256, ND_SMEM>>>(agg, pet, pp_w,
                                            fl_w0, fl_b0, fl_w1, fl_b1, fl_w2, fl_b2,
                                            pooled, out);

    // rigid predictor
    k_rigid<<<1, 128>>>(state, pooled, rg_w0, rg_b0, rg_w1, rg_b1, rg_w2, rg_b2,
                        cent, out);
}

// round 14
// speedup vs baseline: 1.4853x; 1.4853x over previous
#include <cuda_runtime.h>
#include <cuda_bf16.h>
#include <cstdint>

#define NPART 65536
#define NEDGE 524288
#define RIGN  4096

// ---------------- scratch ----------------
constexpr long long O_E1    = 0;
constexpr long long O_E2    = O_E1    + (long long)NEDGE * 128;
constexpr long long O_NODER = O_E2    + (long long)NEDGE * 128;
constexpr long long O_NODES = O_NODER + (long long)NPART * 128;
constexpr long long O_PEH   = O_NODES + (long long)NPART * 128;
constexpr long long O_PE    = O_PEH   + (long long)NPART * 128;
constexpr long long O_PET   = O_PE    + (long long)NPART * 128;
constexpr long long O_EFF   = O_PET   + (long long)NPART * 128;
constexpr long long O_AGG   = O_EFF   + (long long)NPART * 128;
constexpr long long O_POOL  = O_AGG   + (long long)NPART * 128;
constexpr long long O_RIGID = O_POOL  + 128;
constexpr long long O_TOTAL = O_RIGID + 64;

__device__ float g_buf[O_TOTAL];

// ---------------- mma.sync helpers ----------------
__device__ __forceinline__ uint32_t smem_u32(const void* p) {
    uint32_t a;
    asm("{ .reg .u64 t; cvta.to.shared.u64 t, %1; cvt.u32.u64 %0, t; }" : "=r"(a) : "l"(p));
    return a;
}
__device__ __forceinline__ void ldsm4(uint32_t* r, uint32_t addr) {
    asm volatile("ldmatrix.sync.aligned.m8n8.x4.shared.b16 {%0,%1,%2,%3}, [%4];"
        : "=r"(r[0]), "=r"(r[1]), "=r"(r[2]), "=r"(r[3]) : "r"(addr));
}
__device__ __forceinline__ void mma16816(float* c, const uint32_t* a, const uint32_t* b) {
    asm volatile(
        "mma.sync.aligned.m16n8k16.row.col.f32.bf16.bf16.f32 "
        "{%0,%1,%2,%3}, {%4,%5,%6,%7}, {%8,%9}, {%0,%1,%2,%3};"
        : "+f"(c[0]), "+f"(c[1]), "+f"(c[2]), "+f"(c[3])
        : "r"(a[0]), "r"(a[1]), "r"(a[2]), "r"(a[3]), "r"(b[0]), "r"(b[1]));
}
__device__ __forceinline__ void cvt_split(float a, float b, uint32_t& hi, uint32_t& lo) {
    __nv_bfloat162 h = __floats2bfloat162_rn(a, b);
    hi = *(uint32_t*)&h;
    float ra = a - __bfloat162float(h.x);
    float rb = b - __bfloat162float(h.y);
    __nv_bfloat162 l = __floats2bfloat162_rn(ra, rb);
    lo = *(uint32_t*)&l;
}

// byte offset within a 256B-row swizzled tile (16B units XOR row&7)
__device__ __forceinline__ uint32_t sw_off(int row, int unit, int within) {
    return (uint32_t)(row * 256 + (((unit) ^ (row & 7)) << 4) + within);
}

// ---------------- shared fused-MLP machinery (8 warps, 32x32 warp tiles) ----------------
struct MmaCtx {
    uint32_t sb;
    uint32_t baseA0, baseA1, baseB0, baseB1;
    int rxA0, rxA1, rxB0, rxB1, uA0, uB0;
};
__device__ __forceinline__ MmaCtx make_ctx(uint32_t sb, int wm, int wn, int lane) {
    MmaCtx c; c.sb = sb;
    int rowA0 = wm * 32 + (lane & 15), rowA1 = rowA0 + 16;
    c.baseA0 = (uint32_t)(rowA0 * 256); c.baseA1 = (uint32_t)(rowA1 * 256);
    c.rxA0 = rowA0 & 7; c.rxA1 = rowA1 & 7;
    c.uA0 = lane >> 4;
    int rlB = (lane & 7) + ((lane >> 4) << 3);
    c.uB0 = (lane >> 3) & 1;
    int rowB0 = wn * 32 + rlB, rowB1 = rowB0 + 16;
    c.rxB0 = rowB0 & 7; c.rxB1 = rowB1 & 7;
    c.baseB0 = (uint32_t)(rowB0 * 256); c.baseB1 = (uint32_t)(rowB1 * 256);
    return c;
}
__device__ __forceinline__ void mma_layer(const MmaCtx& c, uint32_t actHi, uint32_t actLo,
                                          uint32_t wHi, uint32_t wLo, float acc[2][4][4]) {
#pragma unroll
    for (int mt = 0; mt < 2; mt++)
#pragma unroll
        for (int nt = 0; nt < 4; nt++)
#pragma unroll
            for (int q = 0; q < 4; q++) acc[mt][nt][q] = 0.f;
#pragma unroll
    for (int pass = 0; pass < 3; pass++) {
        uint32_t Ab = c.sb + (pass == 2 ? actLo : actHi);
        uint32_t Bb = c.sb + (pass == 1 ? wLo : wHi);
#pragma unroll
        for (int ks = 0; ks < 8; ks++) {
            uint32_t a0[4], a1[4], f0[4], f1[4];
            ldsm4(a0, Ab + c.baseA0 + ((uint32_t)((ks * 2 + c.uA0) ^ c.rxA0) << 4));
            ldsm4(a1, Ab + c.baseA1 + ((uint32_t)((ks * 2 + c.uA0) ^ c.rxA1) << 4));
            ldsm4(f0, Bb + c.baseB0 + ((uint32_t)((ks * 2 + c.uB0) ^ c.rxB0) << 4));
            ldsm4(f1, Bb + c.baseB1 + ((uint32_t)((ks * 2 + c.uB0) ^ c.rxB1) << 4));
            mma16816(acc[0][0], a0, f0 + 0);
            mma16816(acc[0][1], a0, f0 + 2);
            mma16816(acc[0][2], a0, f1 + 0);
            mma16816(acc[0][3], a0, f1 + 2);
            mma16816(acc[1][0], a1, f0 + 0);
            mma16816(acc[1][1], a1, f0 + 2);
            mma16816(acc[1][2], a1, f1 + 0);
            mma16816(acc[1][3], a1, f1 + 2);
        }
    }
}
// load a 128x128 weight tile (row stride ldw) into hi/lo swizzled tiles (256 threads)
__device__ __forceinline__ void load_weight_tile(char* smem, int dstHi, int dstLo,
                                                 const float* W, int ldw, int tid) {
#pragma unroll
    for (int it = 0; it < 16; it++) {
        int i = tid + it * 256;
        int n = i >> 5, k4 = i & 31;
        float4 v = *(const float4*)(W + (long long)n * ldw + k4 * 4);
        uint32_t h0, l0, h1, l1;
        cvt_split(v.x, v.y, h0, l0);
        cvt_split(v.z, v.w, h1, l1);
        uint32_t off = sw_off(n, k4 >> 1, (k4 & 1) * 8);
        *(uint2*)(smem + dstHi + off) = make_uint2(h0, h1);
        *(uint2*)(smem + dstLo + off) = make_uint2(l0, l1);
    }
}
// load a 64x128 fp32 activation tile (contiguous) into hi/lo swizzled tiles
__device__ __forceinline__ void load_act_tile(char* smem, int actHi, int actLo,
                                              const float* src, int tid) {
    const float4* A4 = (const float4*)src;
#pragma unroll
    for (int it = 0; it < 8; it++) {
        int i = tid + it * 256;
        int row = i >> 5, c4 = i & 31;
        float4 v = A4[i];
        uint32_t h0, l0, h1, l1;
        cvt_split(v.x, v.y, h0, l0);
        cvt_split(v.z, v.w, h1, l1);
        uint32_t off = sw_off(row, c4 >> 1, (c4 & 1) * 8);
        *(uint2*)(smem + actHi + off) = make_uint2(h0, h1);
        *(uint2*)(smem + actLo + off) = make_uint2(l0, l1);
    }
}
// relu(acc + bias) -> activation tile writeback
__device__ __forceinline__ void store_act_relu(char* smem, int actHi, int actLo,
                                               int wm, int wn, int qr, int qc,
                                               float acc[2][4][4], const float* bias) {
#pragma unroll
    for (int mt = 0; mt < 2; mt++) {
        int row0 = wm * 32 + mt * 16 + qr;
        int row1 = row0 + 8;
#pragma unroll
        for (int nt = 0; nt < 4; nt++) {
            int col = wn * 32 + nt * 8 + qc;
            float bx = bias ? bias[col] : 0.f, by = bias ? bias[col + 1] : 0.f;
            float o0 = fmaxf(acc[mt][nt][0] + bx, 0.f);
            float o1 = fmaxf(acc[mt][nt][1] + by, 0.f);
            float o2 = fmaxf(acc[mt][nt][2] + bx, 0.f);
            float o3 = fmaxf(acc[mt][nt][3] + by, 0.f);
            uint32_t h0, l0, h1, l1;
            cvt_split(o0, o1, h0, l0);
            cvt_split(o2, o3, h1, l1);
            uint32_t offA = sw_off(row0, col >> 3, (col & 7) * 2);
            uint32_t offB = sw_off(row1, col >> 3, (col & 7) * 2);
            *(uint32_t*)(smem + actHi + offA) = h0;
            *(uint32_t*)(smem + actLo + offA) = l0;
            *(uint32_t*)(smem + actHi + offB) = h1;
            *(uint32_t*)(smem + actLo + offB) = l1;
        }
    }
}

// ---------------- smem layout ----------------
#define FE_W(L, h)  ((L) * 65536 + (h) * 32768)
#define FE_SA_HI    196608
#define FE_SA_LO    212992
#define FE_CONST    229376
#define FE_SMEM     231936
#define ND_SMEM     232192
#define FE_GRID     148
#define FE_TILES    (NEDGE / 64)
#define ND_TILES    (NPART / 64)
#define RIG_TILES   (RIGN / 64)

// ================= fused edge pipeline (8 warps, 32x32 warp tiles — R10 config) =========
__global__ void __launch_bounds__(256, 1) k_edge_fused(
    const float* __restrict__ nodeR, const float* __restrict__ nodeS,
    const float* __restrict__ Ra, const int* __restrict__ recv, const int* __restrict__ send,
    const float* __restrict__ re_w0, const float* __restrict__ re_b0,
    const float* __restrict__ W1, const float* __restrict__ b1,
    const float* __restrict__ W2, const float* __restrict__ b2,
    const float* __restrict__ W3, const float* __restrict__ b3,
    float* __restrict__ Z, float* __restrict__ agg)
{
    extern __shared__ char smem[];
    uint32_t sb = smem_u32(smem);
    int tid = threadIdx.x;
    int lane = tid & 31, wid = tid >> 5;
    int wm = wid >> 2;
    int wn = wid & 3;
    int qr = lane >> 2, qc = (lane & 3) * 2;

    float* cwra = (float*)(smem + FE_CONST);
    float* cb0  = cwra + 128;
    float* cbl[3] = {cb0 + 128, cb0 + 256, cb0 + 384};

    {
        const float* Ws[3] = {W1, W2, W3};
        const int ldws[3] = {128, 128, 384};
#pragma unroll
        for (int L = 0; L < 3; L++)
            load_weight_tile(smem, FE_W(L, 0), FE_W(L, 1), Ws[L], ldws[L], tid);
        if (tid < 128) {
            cwra[tid] = re_w0[tid * 31 + 30];
            cb0[tid]  = re_b0[tid];
            cbl[0][tid] = b1[tid];
            cbl[1][tid] = b2[tid];
            cbl[2][tid] = b3[tid];
        }
    }
    __syncthreads();

    MmaCtx ctx = make_ctx(sb, wm, wn, lane);

    int e_loc = tid >> 2;
    int c8 = tid & 3;

    float pra;
    float4 pnr[8], pns[8];
    {
        long long eg = (long long)blockIdx.x * 64 + e_loc;
        int r = recv[eg], s = send[eg];
        pra = Ra[eg];
        const float4* nr = (const float4*)(nodeR + (long long)r * 128);
        const float4* ns = (const float4*)(nodeS + (long long)s * 128);
#pragma unroll
        for (int i = 0; i < 8; i++) { pnr[i] = nr[c8 + i * 4]; pns[i] = ns[c8 + i * 4]; }
    }

    for (int t = blockIdx.x; t < FE_TILES; t += FE_GRID) {
        long long ebase = (long long)t * 64;

#pragma unroll
        for (int i = 0; i < 8; i++) {
            int c4 = c8 + i * 4;
            int col = c4 * 4;
            float4 a = pnr[i], b = pns[i];
            float v0 = fmaxf(a.x + b.x + pra * cwra[col + 0] + cb0[col + 0], 0.f);
            float v1 = fmaxf(a.y + b.y + pra * cwra[col + 1] + cb0[col + 1], 0.f);
            float v2 = fmaxf(a.z + b.z + pra * cwra[col + 2] + cb0[col + 2], 0.f);
            float v3 = fmaxf(a.w + b.w + pra * cwra[col + 3] + cb0[col + 3], 0.f);
            uint32_t h0, l0, h1, l1;
            cvt_split(v0, v1, h0, l0);
            cvt_split(v2, v3, h1, l1);
            uint32_t off = sw_off(e_loc, c4 >> 1, (c4 & 1) * 8);
            *(uint2*)(smem + FE_SA_HI + off) = make_uint2(h0, h1);
            *(uint2*)(smem + FE_SA_LO + off) = make_uint2(l0, l1);
        }
        __syncthreads();

#pragma unroll
        for (int L = 0; L < 3; L++) {
            float acc[2][4][4];
            mma_layer(ctx, FE_SA_HI, FE_SA_LO, FE_W(L, 0), FE_W(L, 1), acc);
            __syncthreads();

            if (L < 2) {
                store_act_relu(smem, FE_SA_HI, FE_SA_LO, wm, wn, qr, qc, acc, cbl[L]);
                __syncthreads();
            } else {
                int tn = t + FE_GRID;
                if (tn < FE_TILES) {
                    long long eg = (long long)tn * 64 + e_loc;
                    int r = recv[eg], s = send[eg];
                    pra = Ra[eg];
                    const float4* nr = (const float4*)(nodeR + (long long)r * 128);
                    const float4* ns = (const float4*)(nodeS + (long long)s * 128);
#pragma unroll
                    for (int i = 0; i < 8; i++) { pnr[i] = nr[c8 + i * 4]; pns[i] = ns[c8 + i * 4]; }
                }
#pragma unroll
                for (int mt = 0; mt < 2; mt++) {
                    long long e0 = ebase + wm * 32 + mt * 16 + qr;
                    int rA = recv[e0], rB = recv[e0 + 8];
#pragma unroll
                    for (int nt = 0; nt < 4; nt++) {
                        int col = wn * 32 + nt * 8 + qc;
                        float bx = cbl[2][col], by = cbl[2][col + 1];
                        float o0 = acc[mt][nt][0] + bx, o1 = acc[mt][nt][1] + by;
                        float o2 = acc[mt][nt][2] + bx, o3 = acc[mt][nt][3] + by;
                        *(float2*)(Z + e0 * 128 + col)       = make_float2(o0, o1);
                        *(float2*)(Z + (e0 + 8) * 128 + col) = make_float2(o2, o3);
                        atomicAdd((float2*)(agg + (long long)rA * 128 + col),
                                  make_float2(fmaxf(o0, 0.f), fmaxf(o1, 0.f)));
                        atomicAdd((float2*)(agg + (long long)rB * 128 + col),
                                  make_float2(fmaxf(o2, 0.f), fmaxf(o3, 0.f)));
                    }
                }
            }
        }
    }
}

// ================= fused node prep: pet = relu(peh@pe_w1+pe_b1)@pp_w1 + pp_b =================
__global__ void __launch_bounds__(256, 1) k_node_prep(
    const float* __restrict__ peh,
    const float* __restrict__ pe_w1, const float* __restrict__ pe_b1,
    const float* __restrict__ pp_w, const float* __restrict__ pp_b,
    float* __restrict__ pet)
{
    extern __shared__ char smem[];
    uint32_t sb = smem_u32(smem);
    int tid = threadIdx.x;
    int lane = tid & 31, wid = tid >> 5;
    int wm = wid >> 2, wn = wid & 3;
    int qr = lane >> 2, qc = (lane & 3) * 2;

    float* cb = (float*)(smem + FE_CONST);
    load_weight_tile(smem, FE_W(0, 0), FE_W(0, 1), pe_w1, 128, tid);
    load_weight_tile(smem, FE_W(1, 0), FE_W(1, 1), pp_w, 256, tid);
    if (tid < 128) { cb[tid] = pe_b1[tid]; cb[128 + tid] = pp_b[tid]; }
    __syncthreads();

    MmaCtx ctx = make_ctx(sb, wm, wn, lane);

    for (int t = blockIdx.x; t < ND_TILES; t += FE_GRID) {
        load_act_tile(smem, FE_SA_HI, FE_SA_LO, peh + (long long)t * 64 * 128, tid);
        __syncthreads();

        float acc[2][4][4];
        mma_layer(ctx, FE_SA_HI, FE_SA_LO, FE_W(0, 0), FE_W(0, 1), acc);
        __syncthreads();
        store_act_relu(smem, FE_SA_HI, FE_SA_LO, wm, wn, qr, qc, acc, cb);
        __syncthreads();
        mma_layer(ctx, FE_SA_HI, FE_SA_LO, FE_W(1, 0), FE_W(1, 1), acc);
        __syncthreads();
#pragma unroll
        for (int mt = 0; mt < 2; mt++) {
            long long r0 = (long long)t * 64 + wm * 32 + mt * 16 + qr;
#pragma unroll
            for (int nt = 0; nt < 4; nt++) {
                int col = wn * 32 + nt * 8 + qc;
                float bx = cb[128 + col], by = cb[128 + col + 1];
                *(float2*)(pet + r0 * 128 + col)       = make_float2(acc[mt][nt][0] + bx, acc[mt][nt][1] + by);
                *(float2*)(pet + (r0 + 8) * 128 + col) = make_float2(acc[mt][nt][2] + bx, acc[mt][nt][3] + by);
            }
        }
    }
}

// ================= fused step-1 update + U/V =================
__global__ void __launch_bounds__(256, 1) k_node_step1uv(
    const float* __restrict__ agg, const float* __restrict__ pet,
    const float* __restrict__ pp_w, const float* __restrict__ rp_w,
    float* __restrict__ U, float* __restrict__ V)
{
    extern __shared__ char smem[];
    uint32_t sb = smem_u32(smem);
    int tid = threadIdx.x;
    int lane = tid & 31, wid = tid >> 5;
    int wm = wid >> 2, wn = wid & 3;
    int qr = lane >> 2, qc = (lane & 3) * 2;

    load_weight_tile(smem, FE_W(0, 0), FE_W(0, 1), pp_w + 128, 256, tid);
    load_weight_tile(smem, FE_W(1, 0), FE_W(1, 1), rp_w + 128, 384, tid);
    load_weight_tile(smem, FE_W(2, 0), FE_W(2, 1), rp_w + 256, 384, tid);
    __syncthreads();

    MmaCtx ctx = make_ctx(sb, wm, wn, lane);

    for (int t = blockIdx.x; t < ND_TILES; t += FE_GRID) {
        load_act_tile(smem, FE_SA_HI, FE_SA_LO, agg + (long long)t * 64 * 128, tid);
        __syncthreads();

        float acc[2][4][4];
        mma_layer(ctx, FE_SA_HI, FE_SA_LO, FE_W(0, 0), FE_W(0, 1), acc);
        __syncthreads();
#pragma unroll
        for (int mt = 0; mt < 2; mt++) {
            long long r0 = (long long)t * 64 + wm * 32 + mt * 16 + qr;
#pragma unroll
            for (int nt = 0; nt < 4; nt++) {
                int col = wn * 32 + nt * 8 + qc;
                float2 d0 = *(const float2*)(pet + r0 * 128 + col);
                float2 d1 = *(const float2*)(pet + (r0 + 8) * 128 + col);
                acc[mt][nt][0] += d0.x; acc[mt][nt][1] += d0.y;
                acc[mt][nt][2] += d1.x; acc[mt][nt][3] += d1.y;
            }
        }
        store_act_relu(smem, FE_SA_HI, FE_SA_LO, wm, wn, qr, qc, acc, nullptr);
        __syncthreads();

        mma_layer(ctx, FE_SA_HI, FE_SA_LO, FE_W(1, 0), FE_W(1, 1), acc);
#pragma unroll
        for (int mt = 0; mt < 2; mt++) {
            long long r0 = (long long)t * 64 + wm * 32 + mt * 16 + qr;
#pragma unroll
            for (int nt = 0; nt < 4; nt++) {
                int col = wn * 32 + nt * 8 + qc;
                *(float2*)(U + r0 * 128 + col)       = make_float2(acc[mt][nt][0], acc[mt][nt][1]);
                *(float2*)(U + (r0 + 8) * 128 + col) = make_float2(acc[mt][nt][2], acc[mt][nt][3]);
            }
        }
        mma_layer(ctx, FE_SA_HI, FE_SA_LO, FE_W(2, 0), FE_W(2, 1), acc);
        __syncthreads();
#pragma unroll
        for (int mt = 0; mt < 2; mt++) {
            long long r0 = (long long)t * 64 + wm * 32 + mt * 16 + qr;
#pragma unroll
            for (int nt = 0; nt < 4; nt++) {
                int col = wn * 32 + nt * 8 + qc;
                *(float2*)(V + r0 * 128 + col)       = make_float2(acc[mt][nt][0], acc[mt][nt][1]);
                *(float2*)(V + (r0 + 8) * 128 + col) = make_float2(acc[mt][nt][2], acc[mt][nt][3]);
            }
        }
    }
}

// ================= fused step-2 update + rigid pool + fluid MLP + out =================
__global__ void __launch_bounds__(256, 1) k_node_step2(
    const float* __restrict__ agg, const float* __restrict__ pet,
    const float* __restrict__ pp_w,
    const float* __restrict__ fl_w0, const float* __restrict__ fl_b0,
    const float* __restrict__ fl_w1, const float* __restrict__ fl_b1,
    const float* __restrict__ fl_w2, const float* __restrict__ fl_b2,
    float* __restrict__ pooled, float* __restrict__ out)
{
    extern __shared__ char smem[];
    uint32_t sb = smem_u32(smem);
    int tid = threadIdx.x;
    int lane = tid & 31, wid = tid >> 5;
    int wm = wid >> 2, wn = wid & 3;
    int qr = lane >> 2, qc = (lane & 3) * 2;

    float* cb0 = (float*)(smem + FE_CONST);
    float* cb1 = cb0 + 128;
    float* cw2 = cb1 + 128;
    float* cb2 = cw2 + 384;

    load_weight_tile(smem, FE_W(0, 0), FE_W(0, 1), pp_w + 128, 256, tid);
    load_weight_tile(smem, FE_W(1, 0), FE_W(1, 1), fl_w0, 128, tid);
    load_weight_tile(smem, FE_W(2, 0), FE_W(2, 1), fl_w1, 128, tid);
    if (tid < 128) { cb0[tid] = fl_b0[tid]; cb1[tid] = fl_b1[tid]; }
    if (tid < 128) { cw2[tid] = fl_w2[tid]; cw2[128 + tid] = fl_w2[128 + tid]; cw2[256 + tid] = fl_w2[256 + tid]; }
    if (tid < 3) cb2[tid] = fl_b2[tid];
    __syncthreads();

    MmaCtx ctx = make_ctx(sb, wm, wn, lane);

    for (int t = blockIdx.x; t < ND_TILES; t += FE_GRID) {
        load_act_tile(smem, FE_SA_HI, FE_SA_LO, agg + (long long)t * 64 * 128, tid);
        __syncthreads();

        float acc[2][4][4];
        mma_layer(ctx, FE_SA_HI, FE_SA_LO, FE_W(0, 0), FE_W(0, 1), acc);
        __syncthreads();
#pragma unroll
        for (int mt = 0; mt < 2; mt++) {
            long long r0 = (long long)t * 64 + wm * 32 + mt * 16 + qr;
#pragma unroll
            for (int nt = 0; nt < 4; nt++) {
                int col = wn * 32 + nt * 8 + qc;
                float2 d0 = *(const float2*)(pet + r0 * 128 + col);
                float2 d1 = *(const float2*)(pet + (r0 + 8) * 128 + col);
                acc[mt][nt][0] = fmaxf(acc[mt][nt][0] + d0.x, 0.f);
                acc[mt][nt][1] = fmaxf(acc[mt][nt][1] + d0.y, 0.f);
                acc[mt][nt][2] = fmaxf(acc[mt][nt][2] + d1.x, 0.f);
                acc[mt][nt][3] = fmaxf(acc[mt][nt][3] + d1.y, 0.f);
            }
        }

        if (t < RIG_TILES) {
            float pl[4][2];
#pragma unroll
            for (int nt = 0; nt < 4; nt++) {
                pl[nt][0] = acc[0][nt][0] + acc[0][nt][2] + acc[1][nt][0] + acc[1][nt][2];
                pl[nt][1] = acc[0][nt][1] + acc[0][nt][3] + acc[1][nt][1] + acc[1][nt][3];
            }
#pragma unroll
            for (int nt = 0; nt < 4; nt++) {
                int col = wn * 32 + nt * 8 + qc;
                atomicAdd((float2*)(pooled + col), make_float2(pl[nt][0], pl[nt][1]));
            }
            continue;
        }

#pragma unroll
        for (int mt = 0; mt < 2; mt++) {
            int row0 = wm * 32 + mt * 16 + qr;
            int row1 = row0 + 8;
#pragma unroll
            for (int nt = 0; nt < 4; nt++) {
                int col = wn * 32 + nt * 8 + qc;
                uint32_t h0, l0, h1, l1;
                cvt_split(acc[mt][nt][0], acc[mt][nt][1], h0, l0);
                cvt_split(acc[mt][nt][2], acc[mt][nt][3], h1, l1);
                uint32_t offA = sw_off(row0, col >> 3, (col & 7) * 2);
                uint32_t offB = sw_off(row1, col >> 3, (col & 7) * 2);
                *(uint32_t*)(smem + FE_SA_HI + offA) = h0;
                *(uint32_t*)(smem + FE_SA_LO + offA) = l0;
                *(uint32_t*)(smem + FE_SA_HI + offB) = h1;
                *(uint32_t*)(smem + FE_SA_LO + offB) = l1;
            }
        }
        __syncthreads();

        mma_layer(ctx, FE_SA_HI, FE_SA_LO, FE_W(1, 0), FE_W(1, 1), acc);
        __syncthreads();
        store_act_relu(smem, FE_SA_HI, FE_SA_LO, wm, wn, qr, qc, acc, cb0);
        __syncthreads();
        mma_layer(ctx, FE_SA_HI, FE_SA_LO, FE_W(2, 0), FE_W(2, 1), acc);
        __syncthreads();
        store_act_relu(smem, FE_SA_HI, FE_SA_LO, wm, wn, qr, qc, acc, cb1);
        __syncthreads();

        {
            int row = tid >> 2;
            int q = tid & 3;
            long long g = (long long)t * 64 + row;
            float s0 = 0.f, s1 = 0.f, s2 = 0.f;
#pragma unroll
            for (int j = q * 16; j < q * 16 + 16; j++) {
                uint32_t off = sw_off(row, j >> 2, (j * 4) & 15);
                uint32_t h = *(uint32_t*)(smem + FE_SA_HI + off);
                uint32_t l = *(uint32_t*)(smem + FE_SA_LO + off);
                __nv_bfloat162 hb = *(__nv_bfloat162*)&h;
                __nv_bfloat162 lb = *(__nv_bfloat162*)&l;
                float f0 = __bfloat162float(hb.x) + __bfloat162float(lb.x);
                float f1 = __bfloat162float(hb.y) + __bfloat162float(lb.y);
                int c = 2 * j;
                s0 += f0 * cw2[c] + f1 * cw2[c + 1];
                s1 += f0 * cw2[128 + c] + f1 * cw2[128 + c + 1];
                s2 += f0 * cw2[256 + c] + f1 * cw2[256 + c + 1];
            }
            s0 += __shfl_xor_sync(0xffffffffu, s0, 1); s0 += __shfl_xor_sync(0xffffffffu, s0, 2);
            s1 += __shfl_xor_sync(0xffffffffu, s1, 1); s1 += __shfl_xor_sync(0xffffffffu, s1, 2);
            s2 += __shfl_xor_sync(0xffffffffu, s2, 1); s2 += __shfl_xor_sync(0xffffffffu, s2, 2);
            if (q == 0) {
                out[g * 3 + 0] = s0 + cb2[0];
                out[g * 3 + 1] = s1 + cb2[1];
                out[g * 3 + 2] = s2 + cb2[2];
            }
        }
        __syncthreads();
    }
}

// ---------------- utility ----------------
__global__ void k_zero(float* __restrict__ p, int n) {
    int i = blockIdx.x * blockDim.x + threadIdx.x;
    if (i < n) p[i] = 0.f;
}

__global__ void k_centroid(const float* __restrict__ state, float* __restrict__ cent) {
    float acc[6] = {0, 0, 0, 0, 0, 0};
    for (int i = threadIdx.x; i < RIGN; i += blockDim.x) {
        const float* s = state + i * 6;
#pragma unroll
        for (int c = 0; c < 6; c++) acc[c] += s[c];
    }
    __shared__ float cs[6];
    if (threadIdx.x < 6) cs[threadIdx.x] = 0.f;
    __syncthreads();
#pragma unroll
    for (int c = 0; c < 6; c++) atomicAdd(&cs[c], acc[c]);
    __syncthreads();
    if (threadIdx.x < 6) cent[threadIdx.x] = cs[threadIdx.x] * (1.f / RIGN);
}

// ---------------- node preprocessing ----------------
#define NPB 16
__global__ void __launch_bounds__(128) k_node_pre(
    const float* __restrict__ attr, const float* __restrict__ state,
    const float* __restrict__ pe_w0, const float* __restrict__ pe_b0,
    const float* __restrict__ re_w0, const float* __restrict__ cent,
    float* __restrict__ peh, float* __restrict__ nodeR, float* __restrict__ nodeS)
{
    int tid = threadIdx.x;
    float rpe[15], rR[15], rS[15];
#pragma unroll
    for (int k = 0; k < 15; k++) rpe[k] = pe_w0[tid * 15 + k];
#pragma unroll
    for (int k = 0; k < 9; k++) { rR[k] = re_w0[tid * 31 + k]; rS[k] = re_w0[tid * 31 + 9 + k]; }
#pragma unroll
    for (int k = 0; k < 6; k++) { rR[9 + k] = re_w0[tid * 31 + 18 + k]; rS[9 + k] = re_w0[tid * 31 + 24 + k]; }
    float bpe = pe_b0[tid];
    float c6[6];
#pragma unroll
    for (int c = 0; c < 6; c++) c6[c] = cent[c];

    __shared__ float xin[NPB][9];
    int base = blockIdx.x * NPB;
    for (int j = tid; j < NPB * 9; j += 128) {
        int nd = j / 9, c = j % 9;
        xin[nd][c] = (c < 3) ? attr[(base + nd) * 3 + c] : state[(base + nd) * 6 + (c - 3)];
    }
    __syncthreads();
    for (int nd = 0; nd < NPB; nd++) {
        int g = base + nd;
        float in[15], st[6];
        in[0] = xin[nd][0]; in[1] = xin[nd][1]; in[2] = xin[nd][2];
#pragma unroll
        for (int c = 0; c < 6; c++) {
            st[c] = xin[nd][3 + c];
            in[3 + c] = (g < RIGN) ? (st[c] - c6[c]) : 0.f;
            in[9 + c] = st[c];
        }
        float a0 = bpe, a1 = 0.f, a2 = 0.f;
#pragma unroll
        for (int k = 0; k < 15; k++) a0 = fmaf(in[k], rpe[k], a0);
#pragma unroll
        for (int k = 0; k < 9; k++) { a1 = fmaf(in[k], rR[k], a1); a2 = fmaf(in[k], rS[k], a2); }
#pragma unroll
        for (int k = 0; k < 6; k++) { a1 = fmaf(st[k], rR[9 + k], a1); a2 = fmaf(st[k], rS[9 + k], a2); }
        peh[g * 128 + tid]   = fmaxf(a0, 0.f);
        nodeR[g * 128 + tid] = a1;
        nodeS[g * 128 + tid] = a2;
    }
}

// ---------------- step-2 edge propagation (4 ch/thread, float4 RED) ----------------
__global__ void __launch_bounds__(256) k_edge_prop(
    const float* __restrict__ Z, const float* __restrict__ U, const float* __restrict__ V,
    const int* __restrict__ recv, const int* __restrict__ send,
    float* __restrict__ agg)
{
    long long idx = (long long)blockIdx.x * 256 + threadIdx.x;   // E*32 slots
    int e = (int)(idx >> 5), n4 = (int)(idx & 31) * 4;
    int r = recv[e], s = send[e];
    float4 z = *(const float4*)(Z + (long long)e * 128 + n4);
    float4 u = *(const float4*)(U + (long long)r * 128 + n4);
    float4 v = *(const float4*)(V + (long long)s * 128 + n4);
    float4 w;
    w.x = fmaxf(z.x + u.x + v.x, 0.f);
    w.y = fmaxf(z.y + u.y + v.y, 0.f);
    w.z = fmaxf(z.z + u.z + v.z, 0.f);
    w.w = fmaxf(z.w + u.w + v.w, 0.f);
    atomicAdd((float4*)(agg + (long long)r * 128 + n4), w);
}

// ---------------- rigid branch ----------------
__global__ void __launch_bounds__(128) k_rigid(
    const float* __restrict__ state, const float* __restrict__ pooled,
    const float* __restrict__ w0, const float* __restrict__ b0,
    const float* __restrict__ w1, const float* __restrict__ b1,
    const float* __restrict__ w2, const float* __restrict__ b2,
    const float* __restrict__ cent, float* __restrict__ out)
{
    int tid = threadIdx.x;
    __shared__ float s0[128], s1[128], s2[128], t[7], Rm[9], bb[3], cc[3];
    s0[tid] = pooled[tid] * (1.f / RIGN);
    __syncthreads();
    float a = b0[tid];
    for (int k = 0; k < 128; k++) a = fmaf(s0[k], w0[tid * 128 + k], a);
    s1[tid] = fmaxf(a, 0.f);
    __syncthreads();
    a = b1[tid];
    for (int k = 0; k < 128; k++) a = fmaf(s1[k], w1[tid * 128 + k], a);
    s2[tid] = fmaxf(a, 0.f);
    __syncthreads();
    if (tid < 7) {
        a = b2[tid];
        for (int k = 0; k < 128; k++) a = fmaf(s2[k], w2[tid * 128 + k], a);
        t[tid] = a;
    }
    __syncthreads();
    if (tid == 0) {
        float qn = 1.f / sqrtf(t[0]*t[0] + t[1]*t[1] + t[2]*t[2] + t[3]*t[3]);
        float w = t[0]*qn, x = t[1]*qn, y = t[2]*qn, z = t[3]*qn;
        Rm[0] = 1.f - 2.f*(y*y + z*z); Rm[1] = 2.f*(x*y + z*w);       Rm[2] = 2.f*(x*z - y*w);
        Rm[3] = 2.f*(x*y - z*w);       Rm[4] = 1.f - 2.f*(x*x + z*z); Rm[5] = 2.f*(y*z + x*w);
        Rm[6] = 2.f*(x*z + y*w);       Rm[7] = 2.f*(y*z - x*w);       Rm[8] = 1.f - 2.f*(x*x + y*y);
        bb[0] = t[4]; bb[1] = t[5]; bb[2] = t[6];
        cc[0] = cent[0]; cc[1] = cent[1]; cc[2] = cent[2];
    }
    __syncthreads();
    for (int i = tid; i < RIGN; i += 128) {
        float p0x = state[i*6+0], p0y = state[i*6+1], p0z = state[i*6+2];
        float dx = p0x - cc[0], dy = p0y - cc[1], dz = p0z - cc[2];
        float p1x = dx*Rm[0] + dy*Rm[3] + dz*Rm[6] + bb[0] + cc[0];
        float p1y = dx*Rm[1] + dy*Rm[4] + dz*Rm[7] + bb[1] + cc[1];
        float p1z = dx*Rm[2] + dy*Rm[5] + dz*Rm[8] + bb[2] + cc[2];
        out[i*3+0] = (p1x - p0x) * 60.f;
        out[i*3+1] = (p1y - p0y) * 60.f;
        out[i*3+2] = (p1z - p0z) * 60.f;
    }
}

// ---------------- launch ----------------
extern "C" void kernel_launch(void* const* d_in, const int* in_sizes, int n_in,
                              void* d_out, int out_size)
{
    const float* state = (const float*)d_in[0];
    const float* attr  = (const float*)d_in[1];
    const float* Ra    = (const float*)d_in[2];
    const int*   recv  = (const int*)d_in[3];
    const int*   send  = (const int*)d_in[4];
    const float* pe_w0 = (const float*)d_in[5],  *pe_b0 = (const float*)d_in[6];
    const float* pe_w1 = (const float*)d_in[7],  *pe_b1 = (const float*)d_in[8];
    const float* re_w0 = (const float*)d_in[9],  *re_b0 = (const float*)d_in[10];
    const float* re_w1 = (const float*)d_in[11], *re_b1 = (const float*)d_in[12];
    const float* re_w2 = (const float*)d_in[13], *re_b2 = (const float*)d_in[14];
    const float* rp_w  = (const float*)d_in[15], *rp_b  = (const float*)d_in[16];
    const float* pp_w  = (const float*)d_in[17], *pp_b  = (const float*)d_in[18];
    const float* rg_w0 = (const float*)d_in[19], *rg_b0 = (const float*)d_in[20];
    const float* rg_w1 = (const float*)d_in[21], *rg_b1 = (const float*)d_in[22];
    const float* rg_w2 = (const float*)d_in[23], *rg_b2 = (const float*)d_in[24];
    const float* fl_w0 = (const float*)d_in[25], *fl_b0 = (const float*)d_in[26];
    const float* fl_w1 = (const float*)d_in[27], *fl_b1 = (const float*)d_in[28];
    const float* fl_w2 = (const float*)d_in[29], *fl_b2 = (const float*)d_in[30];
    float* out = (float*)d_out;

    static int smem_set = 0;
    if (!smem_set) {
        cudaFuncSetAttribute(k_edge_fused,   cudaFuncAttributeMaxDynamicSharedMemorySize, FE_SMEM);
        cudaFuncSetAttribute(k_node_prep,    cudaFuncAttributeMaxDynamicSharedMemorySize, ND_SMEM);
        cudaFuncSetAttribute(k_node_step1uv, cudaFuncAttributeMaxDynamicSharedMemorySize, ND_SMEM);
        cudaFuncSetAttribute(k_node_step2,   cudaFuncAttributeMaxDynamicSharedMemorySize, ND_SMEM);
        smem_set = 1;
    }

    void* bp = nullptr;
    cudaGetSymbolAddress(&bp, g_buf);
    float* B     = (float*)bp;
    float* E2    = B + O_E2;      // Z
    float* nodeR = B + O_NODER;   // reused as U
    float* nodeS = B + O_NODES;   // reused as V
    float* peh   = B + O_PEH;
    float* pet   = B + O_PET;
    float* agg   = B + O_AGG;
    float* pooled= B + O_POOL;
    float* cent  = B + O_RIGID;

    const int PG = (NEDGE * 32) / 256;
    const int ZN = (NPART * 128 + 128 + 255) / 256;

    // prep
    k_centroid<<<1, 256>>>(state, cent);
    k_node_pre<<<NPART / NPB, 128>>>(attr, state, pe_w0, pe_b0, re_w0, cent,
                                     peh, nodeR, nodeS);
    k_node_prep<<<FE_GRID, 256, ND_SMEM>>>(peh, pe_w1, pe_b1, pp_w, pp_b, pet);

    // fused edge pipeline: h0 -> re1 -> re2 -> Z (+ step-1 scatter into agg)
    k_zero<<<ZN, 256>>>(agg, NPART * 128 + 128);
    k_edge_fused<<<FE_GRID, 256, FE_SMEM>>>(nodeR, nodeS, Ra, recv, send,
                                            re_w0, re_b0,
                                            re_w1, re_b1, re_w2, re_b2,
                                            rp_w, rp_b, E2, agg);

    // step-1 particle update + U/V (eff never materialized)
    k_node_step1uv<<<FE_GRID, 256, ND_SMEM>>>(agg, pet, pp_w, rp_w, nodeR, nodeS);

    // step-2 propagation
    k_zero<<<ZN, 256>>>(agg, NPART * 128 + 128);     // also zeroes pooled
    k_edge_prop<<<PG, 256>>>(E2, nodeR, nodeS, recv, send, agg);

    // step-2 particle update + rigid pooling + fluid MLP + fluid output
    k_node_step2<<<FE_GRID, 256, ND_SMEM>>>(agg, pet, pp_w,
                                            fl_w0, fl_b0, fl_w1, fl_b1, fl_w2, fl_b2,
                                            pooled, out);

    // rigid predictor
    k_rigid<<<1, 128>>>(state, pooled, rg_w0, rg_b0, rg_w1, rg_b1, rg_w2, rg_b2,
                        cent, out);
}

// round 16
// speedup vs baseline: 1.5722x; 1.0585x over previous
#include <cuda_runtime.h>
#include <cuda_bf16.h>
#include <cstdint>

#define NPART 65536
#define NEDGE 524288
#define RIGN  4096

// ---------------- scratch ----------------
constexpr long long O_E1    = 0;
constexpr long long O_E2    = O_E1    + (long long)NEDGE * 128;
constexpr long long O_NODER = O_E2    + (long long)NEDGE * 128;
constexpr long long O_NODES = O_NODER + (long long)NPART * 128;
constexpr long long O_PEH   = O_NODES + (long long)NPART * 128;
constexpr long long O_PE    = O_PEH   + (long long)NPART * 128;
constexpr long long O_PET   = O_PE    + (long long)NPART * 128;
constexpr long long O_EFF   = O_PET   + (long long)NPART * 128;
constexpr long long O_AGG   = O_EFF   + (long long)NPART * 128;
constexpr long long O_POOL  = O_AGG   + (long long)NPART * 128;
constexpr long long O_RIGID = O_POOL  + 128;
constexpr long long O_TOTAL = O_RIGID + 64;

__device__ float g_buf[O_TOTAL];

// ---------------- mma.sync helpers ----------------
__device__ __forceinline__ uint32_t smem_u32(const void* p) {
    uint32_t a;
    asm("{ .reg .u64 t; cvta.to.shared.u64 t, %1; cvt.u32.u64 %0, t; }" : "=r"(a) : "l"(p));
    return a;
}
__device__ __forceinline__ void ldsm4(uint32_t* r, uint32_t addr) {
    asm volatile("ldmatrix.sync.aligned.m8n8.x4.shared.b16 {%0,%1,%2,%3}, [%4];"
        : "=r"(r[0]), "=r"(r[1]), "=r"(r[2]), "=r"(r[3]) : "r"(addr));
}
__device__ __forceinline__ void mma16816(float* c, const uint32_t* a, const uint32_t* b) {
    asm volatile(
        "mma.sync.aligned.m16n8k16.row.col.f32.bf16.bf16.f32 "
        "{%0,%1,%2,%3}, {%4,%5,%6,%7}, {%8,%9}, {%0,%1,%2,%3};"
        : "+f"(c[0]), "+f"(c[1]), "+f"(c[2]), "+f"(c[3])
        : "r"(a[0]), "r"(a[1]), "r"(a[2]), "r"(a[3]), "r"(b[0]), "r"(b[1]));
}
__device__ __forceinline__ void cvt_split(float a, float b, uint32_t& hi, uint32_t& lo) {
    __nv_bfloat162 h = __floats2bfloat162_rn(a, b);
    hi = *(uint32_t*)&h;
    float ra = a - __bfloat162float(h.x);
    float rb = b - __bfloat162float(h.y);
    __nv_bfloat162 l = __floats2bfloat162_rn(ra, rb);
    lo = *(uint32_t*)&l;
}

// byte offset within a 256B-row swizzled tile (16B units XOR row&7)
__device__ __forceinline__ uint32_t sw_off(int row, int unit, int within) {
    return (uint32_t)(row * 256 + (((unit) ^ (row & 7)) << 4) + within);
}

// named barrier (group-scoped; ids 1,2)
__device__ __forceinline__ void bar_group(int id) {
    asm volatile("bar.sync %0, 128;" :: "r"(id) : "memory");
}

// ---------------- shared fused-MLP machinery (node: 8 warps, 32x32) ----------------
struct MmaCtx {
    uint32_t sb;
    uint32_t baseA0, baseA1, baseB0, baseB1;
    int rxA0, rxA1, rxB0, rxB1, uA0, uB0;
};
__device__ __forceinline__ MmaCtx make_ctx(uint32_t sb, int wm, int wn, int lane) {
    MmaCtx c; c.sb = sb;
    int rowA0 = wm * 32 + (lane & 15), rowA1 = rowA0 + 16;
    c.baseA0 = (uint32_t)(rowA0 * 256); c.baseA1 = (uint32_t)(rowA1 * 256);
    c.rxA0 = rowA0 & 7; c.rxA1 = rowA1 & 7;
    c.uA0 = lane >> 4;
    int rlB = (lane & 7) + ((lane >> 4) << 3);
    c.uB0 = (lane >> 3) & 1;
    int rowB0 = wn * 32 + rlB, rowB1 = rowB0 + 16;
    c.rxB0 = rowB0 & 7; c.rxB1 = rowB1 & 7;
    c.baseB0 = (uint32_t)(rowB0 * 256); c.baseB1 = (uint32_t)(rowB1 * 256);
    return c;
}
__device__ __forceinline__ void mma_layer(const MmaCtx& c, uint32_t actHi, uint32_t actLo,
                                          uint32_t wHi, uint32_t wLo, float acc[2][4][4]) {
#pragma unroll
    for (int mt = 0; mt < 2; mt++)
#pragma unroll
        for (int nt = 0; nt < 4; nt++)
#pragma unroll
            for (int q = 0; q < 4; q++) acc[mt][nt][q] = 0.f;
#pragma unroll
    for (int pass = 0; pass < 3; pass++) {
        uint32_t Ab = c.sb + (pass == 2 ? actLo : actHi);
        uint32_t Bb = c.sb + (pass == 1 ? wLo : wHi);
#pragma unroll
        for (int ks = 0; ks < 8; ks++) {
            uint32_t a0[4], a1[4], f0[4], f1[4];
            ldsm4(a0, Ab + c.baseA0 + ((uint32_t)((ks * 2 + c.uA0) ^ c.rxA0) << 4));
            ldsm4(a1, Ab + c.baseA1 + ((uint32_t)((ks * 2 + c.uA0) ^ c.rxA1) << 4));
            ldsm4(f0, Bb + c.baseB0 + ((uint32_t)((ks * 2 + c.uB0) ^ c.rxB0) << 4));
            ldsm4(f1, Bb + c.baseB1 + ((uint32_t)((ks * 2 + c.uB0) ^ c.rxB1) << 4));
            mma16816(acc[0][0], a0, f0 + 0);
            mma16816(acc[0][1], a0, f0 + 2);
            mma16816(acc[0][2], a0, f1 + 0);
            mma16816(acc[0][3], a0, f1 + 2);
            mma16816(acc[1][0], a1, f0 + 0);
            mma16816(acc[1][1], a1, f0 + 2);
            mma16816(acc[1][2], a1, f1 + 0);
            mma16816(acc[1][3], a1, f1 + 2);
        }
    }
}
// load a 128x128 weight tile (row stride ldw) into hi/lo swizzled tiles (256 threads)
__device__ __forceinline__ void load_weight_tile(char* smem, int dstHi, int dstLo,
                                                 const float* W, int ldw, int tid) {
#pragma unroll
    for (int it = 0; it < 16; it++) {
        int i = tid + it * 256;
        int n = i >> 5, k4 = i & 31;
        float4 v = *(const float4*)(W + (long long)n * ldw + k4 * 4);
        uint32_t h0, l0, h1, l1;
        cvt_split(v.x, v.y, h0, l0);
        cvt_split(v.z, v.w, h1, l1);
        uint32_t off = sw_off(n, k4 >> 1, (k4 & 1) * 8);
        *(uint2*)(smem + dstHi + off) = make_uint2(h0, h1);
        *(uint2*)(smem + dstLo + off) = make_uint2(l0, l1);
    }
}
// load a 64x128 fp32 activation tile (contiguous) into hi/lo swizzled tiles
__device__ __forceinline__ void load_act_tile(char* smem, int actHi, int actLo,
                                              const float* src, int tid) {
    const float4* A4 = (const float4*)src;
#pragma unroll
    for (int it = 0; it < 8; it++) {
        int i = tid + it * 256;
        int row = i >> 5, c4 = i & 31;
        float4 v = A4[i];
        uint32_t h0, l0, h1, l1;
        cvt_split(v.x, v.y, h0, l0);
        cvt_split(v.z, v.w, h1, l1);
        uint32_t off = sw_off(row, c4 >> 1, (c4 & 1) * 8);
        *(uint2*)(smem + actHi + off) = make_uint2(h0, h1);
        *(uint2*)(smem + actLo + off) = make_uint2(l0, l1);
    }
}
// relu(acc + bias) -> activation tile writeback
__device__ __forceinline__ void store_act_relu(char* smem, int actHi, int actLo,
                                               int wm, int wn, int qr, int qc,
                                               float acc[2][4][4], const float* bias) {
#pragma unroll
    for (int mt = 0; mt < 2; mt++) {
        int row0 = wm * 32 + mt * 16 + qr;
        int row1 = row0 + 8;
#pragma unroll
        for (int nt = 0; nt < 4; nt++) {
            int col = wn * 32 + nt * 8 + qc;
            float bx = bias ? bias[col] : 0.f, by = bias ? bias[col + 1] : 0.f;
            float o0 = fmaxf(acc[mt][nt][0] + bx, 0.f);
            float o1 = fmaxf(acc[mt][nt][1] + by, 0.f);
            float o2 = fmaxf(acc[mt][nt][2] + bx, 0.f);
            float o3 = fmaxf(acc[mt][nt][3] + by, 0.f);
            uint32_t h0, l0, h1, l1;
            cvt_split(o0, o1, h0, l0);
            cvt_split(o2, o3, h1, l1);
            uint32_t offA = sw_off(row0, col >> 3, (col & 7) * 2);
            uint32_t offB = sw_off(row1, col >> 3, (col & 7) * 2);
            *(uint32_t*)(smem + actHi + offA) = h0;
            *(uint32_t*)(smem + actLo + offA) = l0;
            *(uint32_t*)(smem + actHi + offB) = h1;
            *(uint32_t*)(smem + actLo + offB) = l1;
        }
    }
}

// ---------------- smem layout ----------------
#define FE_W(L, h)  ((L) * 65536 + (h) * 32768)
#define FE_SA_HI    196608
#define FE_SA_LO    212992
#define FE_CONST    229376
#define FE_SMEM     231936
#define ND_SMEM     232192
#define FE_GRID     148
#define ND_TILES    (NPART / 64)
#define RIG_TILES   (RIGN / 64)

// ================= fused edge pipeline: two independent 4-warp groups =================
// Each group processes 32-edge tiles with its own 8KB hi/lo act buffer; weights shared.
#define FE_TILES32  (NEDGE / 32)
__global__ void __launch_bounds__(256, 1) k_edge_fused(
    const float* __restrict__ nodeR, const float* __restrict__ nodeS,
    const float* __restrict__ Ra, const int* __restrict__ recv, const int* __restrict__ send,
    const float* __restrict__ re_w0, const float* __restrict__ re_b0,
    const float* __restrict__ W1, const float* __restrict__ b1,
    const float* __restrict__ W2, const float* __restrict__ b2,
    const float* __restrict__ W3, const float* __restrict__ b3,
    float* __restrict__ Z, float* __restrict__ agg)
{
    extern __shared__ char smem[];
    uint32_t sb = smem_u32(smem);
    int tid = threadIdx.x;
    int g = tid >> 7;            // group 0/1
    int gtid = tid & 127;
    int lane = tid & 31;
    int wn = (tid >> 5) & 3;     // warp within group: 4 n-groups of 32 cols
    int qr = lane >> 2, qc = (lane & 3) * 2;

    float* cwra = (float*)(smem + FE_CONST);
    float* cb0  = cwra + 128;
    float* cbl[3] = {cb0 + 128, cb0 + 256, cb0 + 384};

    {
        const float* Ws[3] = {W1, W2, W3};
        const int ldws[3] = {128, 128, 384};
#pragma unroll
        for (int L = 0; L < 3; L++)
            load_weight_tile(smem, FE_W(L, 0), FE_W(L, 1), Ws[L], ldws[L], tid);
        if (tid < 128) {
            cwra[tid] = re_w0[tid * 31 + 30];
            cb0[tid]  = re_b0[tid];
            cbl[0][tid] = b1[tid];
            cbl[1][tid] = b2[tid];
            cbl[2][tid] = b3[tid];
        }
    }
    __syncthreads();

    // group-private activation buffers (8KB each half)
    uint32_t actHi = FE_SA_HI + g * 8192;
    uint32_t actLo = FE_SA_LO + g * 8192;
    int barid = g + 1;

    // mma lane addressing: A rows 0..31 within group tile, B = weight cols wn*32..+31
    int rowA0 = lane & 15, rowA1 = rowA0 + 16;
    uint32_t baseA0 = (uint32_t)(rowA0 * 256), baseA1 = (uint32_t)(rowA1 * 256);
    int rxA0 = rowA0 & 7, rxA1 = rowA1 & 7;
    int uA0 = lane >> 4;
    int rlB = (lane & 7) + ((lane >> 4) << 3);
    int uB0 = (lane >> 3) & 1;
    int rowB0 = wn * 32 + rlB,      rxB0 = rowB0 & 7;
    int rowB1 = wn * 32 + 16 + rlB, rxB1 = rowB1 & 7;
    uint32_t baseB0 = (uint32_t)(rowB0 * 256), baseB1 = (uint32_t)(rowB1 * 256);

    int e_loc = gtid >> 2;     // 32 edges, 4 threads each
    int c8 = gtid & 3;

    int gid = blockIdx.x * 2 + g;
    for (int t = gid; t < FE_TILES32; t += FE_GRID * 2) {
        long long ebase = (long long)t * 32;

        // ---- gather h0 tile (32 edges) ----
        {
            long long eg = ebase + e_loc;
            int r = recv[eg], s = send[eg];
            float ra = Ra[eg];
            const float4* nr = (const float4*)(nodeR + (long long)r * 128);
            const float4* ns = (const float4*)(nodeS + (long long)s * 128);
#pragma unroll
            for (int i = 0; i < 8; i++) {
                int c4 = c8 + i * 4;
                int col = c4 * 4;
                float4 a = nr[c4];
                float4 b = ns[c4];
                float v0 = fmaxf(a.x + b.x + ra * cwra[col + 0] + cb0[col + 0], 0.f);
                float v1 = fmaxf(a.y + b.y + ra * cwra[col + 1] + cb0[col + 1], 0.f);
                float v2 = fmaxf(a.z + b.z + ra * cwra[col + 2] + cb0[col + 2], 0.f);
                float v3 = fmaxf(a.w + b.w + ra * cwra[col + 3] + cb0[col + 3], 0.f);
                uint32_t h0, l0, h1, l1;
                cvt_split(v0, v1, h0, l0);
                cvt_split(v2, v3, h1, l1);
                uint32_t off = sw_off(e_loc, c4 >> 1, (c4 & 1) * 8);
                *(uint2*)(smem + actHi + off) = make_uint2(h0, h1);
                *(uint2*)(smem + actLo + off) = make_uint2(l0, l1);
            }
        }
        bar_group(barid);

#pragma unroll
        for (int L = 0; L < 3; L++) {
            float acc[2][4][4];
#pragma unroll
            for (int mt = 0; mt < 2; mt++)
#pragma unroll
                for (int nt = 0; nt < 4; nt++)
#pragma unroll
                    for (int q = 0; q < 4; q++) acc[mt][nt][q] = 0.f;

#pragma unroll
            for (int pass = 0; pass < 3; pass++) {
                uint32_t Ab = sb + (pass == 2 ? actLo : actHi);
                uint32_t Bb = sb + FE_W(L, pass == 1 ? 1 : 0);
#pragma unroll
                for (int ks = 0; ks < 8; ks++) {
                    uint32_t a0[4], a1[4], f0[4], f1[4];
                    ldsm4(a0, Ab + baseA0 + ((uint32_t)((ks * 2 + uA0) ^ rxA0) << 4));
                    ldsm4(a1, Ab + baseA1 + ((uint32_t)((ks * 2 + uA0) ^ rxA1) << 4));
                    ldsm4(f0, Bb + baseB0 + ((uint32_t)((ks * 2 + uB0) ^ rxB0) << 4));
                    ldsm4(f1, Bb + baseB1 + ((uint32_t)((ks * 2 + uB0) ^ rxB1) << 4));
                    mma16816(acc[0][0], a0, f0 + 0);
                    mma16816(acc[0][1], a0, f0 + 2);
                    mma16816(acc[0][2], a0, f1 + 0);
                    mma16816(acc[0][3], a0, f1 + 2);
                    mma16816(acc[1][0], a1, f0 + 0);
                    mma16816(acc[1][1], a1, f0 + 2);
                    mma16816(acc[1][2], a1, f1 + 0);
                    mma16816(acc[1][3], a1, f1 + 2);
                }
            }
            bar_group(barid);

            if (L < 2) {
#pragma unroll
                for (int mt = 0; mt < 2; mt++) {
                    int row0 = mt * 16 + qr;
                    int row1 = row0 + 8;
#pragma unroll
                    for (int nt = 0; nt < 4; nt++) {
                        int col = wn * 32 + nt * 8 + qc;
                        float bx = cbl[L][col], by = cbl[L][col + 1];
                        float o0 = fmaxf(acc[mt][nt][0] + bx, 0.f);
                        float o1 = fmaxf(acc[mt][nt][1] + by, 0.f);
                        float o2 = fmaxf(acc[mt][nt][2] + bx, 0.f);
                        float o3 = fmaxf(acc[mt][nt][3] + by, 0.f);
                        uint32_t h0, l0, h1, l1;
                        cvt_split(o0, o1, h0, l0);
                        cvt_split(o2, o3, h1, l1);
                        uint32_t offA = sw_off(row0, col >> 3, (col & 7) * 2);
                        uint32_t offB = sw_off(row1, col >> 3, (col & 7) * 2);
                        *(uint32_t*)(smem + actHi + offA) = h0;
                        *(uint32_t*)(smem + actLo + offA) = l0;
                        *(uint32_t*)(smem + actHi + offB) = h1;
                        *(uint32_t*)(smem + actLo + offB) = l1;
                    }
                }
                bar_group(barid);
            } else {
                // Z store + fused step-1 scatter (act not read here)
#pragma unroll
                for (int mt = 0; mt < 2; mt++) {
                    long long e0 = ebase + mt * 16 + qr;
                    int rA = recv[e0], rB = recv[e0 + 8];
#pragma unroll
                    for (int nt = 0; nt < 4; nt++) {
                        int col = wn * 32 + nt * 8 + qc;
                        float bx = cbl[2][col], by = cbl[2][col + 1];
                        float o0 = acc[mt][nt][0] + bx, o1 = acc[mt][nt][1] + by;
                        float o2 = acc[mt][nt][2] + bx, o3 = acc[mt][nt][3] + by;
                        *(float2*)(Z + e0 * 128 + col)       = make_float2(o0, o1);
                        *(float2*)(Z + (e0 + 8) * 128 + col) = make_float2(o2, o3);
                        atomicAdd((float2*)(agg + (long long)rA * 128 + col),
                                  make_float2(fmaxf(o0, 0.f), fmaxf(o1, 0.f)));
                        atomicAdd((float2*)(agg + (long long)rB * 128 + col),
                                  make_float2(fmaxf(o2, 0.f), fmaxf(o3, 0.f)));
                    }
                }
            }
        }
    }
}

// ================= fused node prep: pet = relu(peh@pe_w1+pe_b1)@pp_w1 + pp_b =================
__global__ void __launch_bounds__(256, 1) k_node_prep(
    const float* __restrict__ peh,
    const float* __restrict__ pe_w1, const float* __restrict__ pe_b1,
    const float* __restrict__ pp_w, const float* __restrict__ pp_b,
    float* __restrict__ pet)
{
    extern __shared__ char smem[];
    uint32_t sb = smem_u32(smem);
    int tid = threadIdx.x;
    int lane = tid & 31, wid = tid >> 5;
    int wm = wid >> 2, wn = wid & 3;
    int qr = lane >> 2, qc = (lane & 3) * 2;

    float* cb = (float*)(smem + FE_CONST);
    load_weight_tile(smem, FE_W(0, 0), FE_W(0, 1), pe_w1, 128, tid);
    load_weight_tile(smem, FE_W(1, 0), FE_W(1, 1), pp_w, 256, tid);
    if (tid < 128) { cb[tid] = pe_b1[tid]; cb[128 + tid] = pp_b[tid]; }
    __syncthreads();

    MmaCtx ctx = make_ctx(sb, wm, wn, lane);

    for (int t = blockIdx.x; t < ND_TILES; t += FE_GRID) {
        load_act_tile(smem, FE_SA_HI, FE_SA_LO, peh + (long long)t * 64 * 128, tid);
        __syncthreads();

        float acc[2][4][4];
        mma_layer(ctx, FE_SA_HI, FE_SA_LO, FE_W(0, 0), FE_W(0, 1), acc);
        __syncthreads();
        store_act_relu(smem, FE_SA_HI, FE_SA_LO, wm, wn, qr, qc, acc, cb);
        __syncthreads();
        mma_layer(ctx, FE_SA_HI, FE_SA_LO, FE_W(1, 0), FE_W(1, 1), acc);
        __syncthreads();
#pragma unroll
        for (int mt = 0; mt < 2; mt++) {
            long long r0 = (long long)t * 64 + wm * 32 + mt * 16 + qr;
#pragma unroll
            for (int nt = 0; nt < 4; nt++) {
                int col = wn * 32 + nt * 8 + qc;
                float bx = cb[128 + col], by = cb[128 + col + 1];
                *(float2*)(pet + r0 * 128 + col)       = make_float2(acc[mt][nt][0] + bx, acc[mt][nt][1] + by);
                *(float2*)(pet + (r0 + 8) * 128 + col) = make_float2(acc[mt][nt][2] + bx, acc[mt][nt][3] + by);
            }
        }
    }
}

// ================= fused step-1 update + U/V =================
__global__ void __launch_bounds__(256, 1) k_node_step1uv(
    const float* __restrict__ agg, const float* __restrict__ pet,
    const float* __restrict__ pp_w, const float* __restrict__ rp_w,
    float* __restrict__ U, float* __restrict__ V)
{
    extern __shared__ char smem[];
    uint32_t sb = smem_u32(smem);
    int tid = threadIdx.x;
    int lane = tid & 31, wid = tid >> 5;
    int wm = wid >> 2, wn = wid & 3;
    int qr = lane >> 2, qc = (lane & 3) * 2;

    load_weight_tile(smem, FE_W(0, 0), FE_W(0, 1), pp_w + 128, 256, tid);
    load_weight_tile(smem, FE_W(1, 0), FE_W(1, 1), rp_w + 128, 384, tid);
    load_weight_tile(smem, FE_W(2, 0), FE_W(2, 1), rp_w + 256, 384, tid);
    __syncthreads();

    MmaCtx ctx = make_ctx(sb, wm, wn, lane);

    for (int t = blockIdx.x; t < ND_TILES; t += FE_GRID) {
        load_act_tile(smem, FE_SA_HI, FE_SA_LO, agg + (long long)t * 64 * 128, tid);
        __syncthreads();

        float acc[2][4][4];
        mma_layer(ctx, FE_SA_HI, FE_SA_LO, FE_W(0, 0), FE_W(0, 1), acc);
        __syncthreads();
#pragma unroll
        for (int mt = 0; mt < 2; mt++) {
            long long r0 = (long long)t * 64 + wm * 32 + mt * 16 + qr;
#pragma unroll
            for (int nt = 0; nt < 4; nt++) {
                int col = wn * 32 + nt * 8 + qc;
                float2 d0 = *(const float2*)(pet + r0 * 128 + col);
                float2 d1 = *(const float2*)(pet + (r0 + 8) * 128 + col);
                acc[mt][nt][0] += d0.x; acc[mt][nt][1] += d0.y;
                acc[mt][nt][2] += d1.x; acc[mt][nt][3] += d1.y;
            }
        }
        store_act_relu(smem, FE_SA_HI, FE_SA_LO, wm, wn, qr, qc, acc, nullptr);
        __syncthreads();

        mma_layer(ctx, FE_SA_HI, FE_SA_LO, FE_W(1, 0), FE_W(1, 1), acc);
#pragma unroll
        for (int mt = 0; mt < 2; mt++) {
            long long r0 = (long long)t * 64 + wm * 32 + mt * 16 + qr;
#pragma unroll
            for (int nt = 0; nt < 4; nt++) {
                int col = wn * 32 + nt * 8 + qc;
                *(float2*)(U + r0 * 128 + col)       = make_float2(acc[mt][nt][0], acc[mt][nt][1]);
                *(float2*)(U + (r0 + 8) * 128 + col) = make_float2(acc[mt][nt][2], acc[mt][nt][3]);
            }
        }
        mma_layer(ctx, FE_SA_HI, FE_SA_LO, FE_W(2, 0), FE_W(2, 1), acc);
        __syncthreads();
#pragma unroll
        for (int mt = 0; mt < 2; mt++) {
            long long r0 = (long long)t * 64 + wm * 32 + mt * 16 + qr;
#pragma unroll
            for (int nt = 0; nt < 4; nt++) {
                int col = wn * 32 + nt * 8 + qc;
                *(float2*)(V + r0 * 128 + col)       = make_float2(acc[mt][nt][0], acc[mt][nt][1]);
                *(float2*)(V + (r0 + 8) * 128 + col) = make_float2(acc[mt][nt][2], acc[mt][nt][3]);
            }
        }
    }
}

// ================= fused step-2 update + rigid pool + fluid MLP + out =================
__global__ void __launch_bounds__(256, 1) k_node_step2(
    const float* __restrict__ agg, const float* __restrict__ pet,
    const float* __restrict__ pp_w,
    const float* __restrict__ fl_w0, const float* __restrict__ fl_b0,
    const float* __restrict__ fl_w1, const float* __restrict__ fl_b1,
    const float* __restrict__ fl_w2, const float* __restrict__ fl_b2,
    float* __restrict__ pooled, float* __restrict__ out)
{
    extern __shared__ char smem[];
    uint32_t sb = smem_u32(smem);
    int tid = threadIdx.x;
    int lane = tid & 31, wid = tid >> 5;
    int wm = wid >> 2, wn = wid & 3;
    int qr = lane >> 2, qc = (lane & 3) * 2;

    float* cb0 = (float*)(smem + FE_CONST);
    float* cb1 = cb0 + 128;
    float* cw2 = cb1 + 128;
    float* cb2 = cw2 + 384;

    load_weight_tile(smem, FE_W(0, 0), FE_W(0, 1), pp_w + 128, 256, tid);
    load_weight_tile(smem, FE_W(1, 0), FE_W(1, 1), fl_w0, 128, tid);
    load_weight_tile(smem, FE_W(2, 0), FE_W(2, 1), fl_w1, 128, tid);
    if (tid < 128) { cb0[tid] = fl_b0[tid]; cb1[tid] = fl_b1[tid]; }
    if (tid < 128) { cw2[tid] = fl_w2[tid]; cw2[128 + tid] = fl_w2[128 + tid]; cw2[256 + tid] = fl_w2[256 + tid]; }
    if (tid < 3) cb2[tid] = fl_b2[tid];
    __syncthreads();

    MmaCtx ctx = make_ctx(sb, wm, wn, lane);

    for (int t = blockIdx.x; t < ND_TILES; t += FE_GRID) {
        load_act_tile(smem, FE_SA_HI, FE_SA_LO, agg + (long long)t * 64 * 128, tid);
        __syncthreads();

        float acc[2][4][4];
        mma_layer(ctx, FE_SA_HI, FE_SA_LO, FE_W(0, 0), FE_W(0, 1), acc);
        __syncthreads();
#pragma unroll
        for (int mt = 0; mt < 2; mt++) {
            long long r0 = (long long)t * 64 + wm * 32 + mt * 16 + qr;
#pragma unroll
            for (int nt = 0; nt < 4; nt++) {
                int col = wn * 32 + nt * 8 + qc;
                float2 d0 = *(const float2*)(pet + r0 * 128 + col);
                float2 d1 = *(const float2*)(pet + (r0 + 8) * 128 + col);
                acc[mt][nt][0] = fmaxf(acc[mt][nt][0] + d0.x, 0.f);
                acc[mt][nt][1] = fmaxf(acc[mt][nt][1] + d0.y, 0.f);
                acc[mt][nt][2] = fmaxf(acc[mt][nt][2] + d1.x, 0.f);
                acc[mt][nt][3] = fmaxf(acc[mt][nt][3] + d1.y, 0.f);
            }
        }

        if (t < RIG_TILES) {
            float pl[4][2];
#pragma unroll
            for (int nt = 0; nt < 4; nt++) {
                pl[nt][0] = acc[0][nt][0] + acc[0][nt][2] + acc[1][nt][0] + acc[1][nt][2];
                pl[nt][1] = acc[0][nt][1] + acc[0][nt][3] + acc[1][nt][1] + acc[1][nt][3];
            }
#pragma unroll
            for (int nt = 0; nt < 4; nt++) {
                int col = wn * 32 + nt * 8 + qc;
                atomicAdd((float2*)(pooled + col), make_float2(pl[nt][0], pl[nt][1]));
            }
            continue;
        }

#pragma unroll
        for (int mt = 0; mt < 2; mt++) {
            int row0 = wm * 32 + mt * 16 + qr;
            int row1 = row0 + 8;
#pragma unroll
            for (int nt = 0; nt < 4; nt++) {
                int col = wn * 32 + nt * 8 + qc;
                uint32_t h0, l0, h1, l1;
                cvt_split(acc[mt][nt][0], acc[mt][nt][1], h0, l0);
                cvt_split(acc[mt][nt][2], acc[mt][nt][3], h1, l1);
                uint32_t offA = sw_off(row0, col >> 3, (col & 7) * 2);
                uint32_t offB = sw_off(row1, col >> 3, (col & 7) * 2);
                *(uint32_t*)(smem + FE_SA_HI + offA) = h0;
                *(uint32_t*)(smem + FE_SA_LO + offA) = l0;
                *(uint32_t*)(smem + FE_SA_HI + offB) = h1;
                *(uint32_t*)(smem + FE_SA_LO + offB) = l1;
            }
        }
        __syncthreads();

        mma_layer(ctx, FE_SA_HI, FE_SA_LO, FE_W(1, 0), FE_W(1, 1), acc);
        __syncthreads();
        store_act_relu(smem, FE_SA_HI, FE_SA_LO, wm, wn, qr, qc, acc, cb0);
        __syncthreads();
        mma_layer(ctx, FE_SA_HI, FE_SA_LO, FE_W(2, 0), FE_W(2, 1), acc);
        __syncthreads();
        store_act_relu(smem, FE_SA_HI, FE_SA_LO, wm, wn, qr, qc, acc, cb1);
        __syncthreads();

        {
            int row = tid >> 2;
            int q = tid & 3;
            long long g = (long long)t * 64 + row;
            float s0 = 0.f, s1 = 0.f, s2 = 0.f;
#pragma unroll
            for (int j = q * 16; j < q * 16 + 16; j++) {
                uint32_t off = sw_off(row, j >> 2, (j * 4) & 15);
                uint32_t h = *(uint32_t*)(smem + FE_SA_HI + off);
                uint32_t l = *(uint32_t*)(smem + FE_SA_LO + off);
                __nv_bfloat162 hb = *(__nv_bfloat162*)&h;
                __nv_bfloat162 lb = *(__nv_bfloat162*)&l;
                float f0 = __bfloat162float(hb.x) + __bfloat162float(lb.x);
                float f1 = __bfloat162float(hb.y) + __bfloat162float(lb.y);
                int c = 2 * j;
                s0 += f0 * cw2[c] + f1 * cw2[c + 1];
                s1 += f0 * cw2[128 + c] + f1 * cw2[128 + c + 1];
                s2 += f0 * cw2[256 + c] + f1 * cw2[256 + c + 1];
            }
            s0 += __shfl_xor_sync(0xffffffffu, s0, 1); s0 += __shfl_xor_sync(0xffffffffu, s0, 2);
            s1 += __shfl_xor_sync(0xffffffffu, s1, 1); s1 += __shfl_xor_sync(0xffffffffu, s1, 2);
            s2 += __shfl_xor_sync(0xffffffffu, s2, 1); s2 += __shfl_xor_sync(0xffffffffu, s2, 2);
            if (q == 0) {
                out[g * 3 + 0] = s0 + cb2[0];
                out[g * 3 + 1] = s1 + cb2[1];
                out[g * 3 + 2] = s2 + cb2[2];
            }
        }
        __syncthreads();
    }
}

// ---------------- utility ----------------
__global__ void k_zero(float* __restrict__ p, int n) {
    int i = blockIdx.x * blockDim.x + threadIdx.x;
    if (i < n) p[i] = 0.f;
}

__global__ void k_centroid(const float* __restrict__ state, float* __restrict__ cent) {
    float acc[6] = {0, 0, 0, 0, 0, 0};
    for (int i = threadIdx.x; i < RIGN; i += blockDim.x) {
        const float* s = state + i * 6;
#pragma unroll
        for (int c = 0; c < 6; c++) acc[c] += s[c];
    }
    __shared__ float cs[6];
    if (threadIdx.x < 6) cs[threadIdx.x] = 0.f;
    __syncthreads();
#pragma unroll
    for (int c = 0; c < 6; c++) atomicAdd(&cs[c], acc[c]);
    __syncthreads();
    if (threadIdx.x < 6) cent[threadIdx.x] = cs[threadIdx.x] * (1.f / RIGN);
}

// ---------------- node preprocessing ----------------
#define NPB 16
__global__ void __launch_bounds__(128) k_node_pre(
    const float* __restrict__ attr, const float* __restrict__ state,
    const float* __restrict__ pe_w0, const float* __restrict__ pe_b0,
    const float* __restrict__ re_w0, const float* __restrict__ cent,
    float* __restrict__ peh, float* __restrict__ nodeR, float* __restrict__ nodeS)
{
    int tid = threadIdx.x;
    float rpe[15], rR[15], rS[15];
#pragma unroll
    for (int k = 0; k < 15; k++) rpe[k] = pe_w0[tid * 15 + k];
#pragma unroll
    for (int k = 0; k < 9; k++) { rR[k] = re_w0[tid * 31 + k]; rS[k] = re_w0[tid * 31 + 9 + k]; }
#pragma unroll
    for (int k = 0; k < 6; k++) { rR[9 + k] = re_w0[tid * 31 + 18 + k]; rS[9 + k] = re_w0[tid * 31 + 24 + k]; }
    float bpe = pe_b0[tid];
    float c6[6];
#pragma unroll
    for (int c = 0; c < 6; c++) c6[c] = cent[c];

    __shared__ float xin[NPB][9];
    int base = blockIdx.x * NPB;
    for (int j = tid; j < NPB * 9; j += 128) {
        int nd = j / 9, c = j % 9;
        xin[nd][c] = (c < 3) ? attr[(base + nd) * 3 + c] : state[(base + nd) * 6 + (c - 3)];
    }
    __syncthreads();
    for (int nd = 0; nd < NPB; nd++) {
        int g = base + nd;
        float in[15], st[6];
        in[0] = xin[nd][0]; in[1] = xin[nd][1]; in[2] = xin[nd][2];
#pragma unroll
        for (int c = 0; c < 6; c++) {
            st[c] = xin[nd][3 + c];
            in[3 + c] = (g < RIGN) ? (st[c] - c6[c]) : 0.f;
            in[9 + c] = st[c];
        }
        float a0 = bpe, a1 = 0.f, a2 = 0.f;
#pragma unroll
        for (int k = 0; k < 15; k++) a0 = fmaf(in[k], rpe[k], a0);
#pragma unroll
        for (int k = 0; k < 9; k++) { a1 = fmaf(in[k], rR[k], a1); a2 = fmaf(in[k], rS[k], a2); }
#pragma unroll
        for (int k = 0; k < 6; k++) { a1 = fmaf(st[k], rR[9 + k], a1); a2 = fmaf(st[k], rS[9 + k], a2); }
        peh[g * 128 + tid]   = fmaxf(a0, 0.f);
        nodeR[g * 128 + tid] = a1;
        nodeS[g * 128 + tid] = a2;
    }
}

// ---------------- step-2 edge propagation (4 ch/thread, float4 RED) ----------------
__global__ void __launch_bounds__(256) k_edge_prop(
    const float* __restrict__ Z, const float* __restrict__ U, const float* __restrict__ V,
    const int* __restrict__ recv, const int* __restrict__ send,
    float* __restrict__ agg)
{
    long long idx = (long long)blockIdx.x * 256 + threadIdx.x;   // E*32 slots
    int e = (int)(idx >> 5), n4 = (int)(idx & 31) * 4;
    int r = recv[e], s = send[e];
    float4 z = *(const float4*)(Z + (long long)e * 128 + n4);
    float4 u = *(const float4*)(U + (long long)r * 128 + n4);
    float4 v = *(const float4*)(V + (long long)s * 128 + n4);
    float4 w;
    w.x = fmaxf(z.x + u.x + v.x, 0.f);
    w.y = fmaxf(z.y + u.y + v.y, 0.f);
    w.z = fmaxf(z.z + u.z + v.z, 0.f);
    w.w = fmaxf(z.w + u.w + v.w, 0.f);
    atomicAdd((float4*)(agg + (long long)r * 128 + n4), w);
}

// ---------------- rigid branch ----------------
__global__ void __launch_bounds__(128) k_rigid(
    const float* __restrict__ state, const float* __restrict__ pooled,
    const float* __restrict__ w0, const float* __restrict__ b0,
    const float* __restrict__ w1, const float* __restrict__ b1,
    const float* __restrict__ w2, const float* __restrict__ b2,
    const float* __restrict__ cent, float* __restrict__ out)
{
    int tid = threadIdx.x;
    __shared__ float s0[128], s1[128], s2[128], t[7], Rm[9], bb[3], cc[3];
    s0[tid] = pooled[tid] * (1.f / RIGN);
    __syncthreads();
    float a = b0[tid];
    for (int k = 0; k < 128; k++) a = fmaf(s0[k], w0[tid * 128 + k], a);
    s1[tid] = fmaxf(a, 0.f);
    __syncthreads();
    a = b1[tid];
    for (int k = 0; k < 128; k++) a = fmaf(s1[k], w1[tid * 128 + k], a);
    s2[tid] = fmaxf(a, 0.f);
    __syncthreads();
    if (tid < 7) {
        a = b2[tid];
        for (int k = 0; k < 128; k++) a = fmaf(s2[k], w2[tid * 128 + k], a);
        t[tid] = a;
    }
    __syncthreads();
    if (tid == 0) {
        float qn = 1.f / sqrtf(t[0]*t[0] + t[1]*t[1] + t[2]*t[2] + t[3]*t[3]);
        float w = t[0]*qn, x = t[1]*qn, y = t[2]*qn, z = t[3]*qn;
        Rm[0] = 1.f - 2.f*(y*y + z*z); Rm[1] = 2.f*(x*y + z*w);       Rm[2] = 2.f*(x*z - y*w);
        Rm[3] = 2.f*(x*y - z*w);       Rm[4] = 1.f - 2.f*(x*x + z*z); Rm[5] = 2.f*(y*z + x*w);
        Rm[6] = 2.f*(x*z + y*w);       Rm[7] = 2.f*(y*z - x*w);       Rm[8] = 1.f - 2.f*(x*x + y*y);
        bb[0] = t[4]; bb[1] = t[5]; bb[2] = t[6];
        cc[0] = cent[0]; cc[1] = cent[1]; cc[2] = cent[2];
    }
    __syncthreads();
    for (int i = tid; i < RIGN; i += 128) {
        float p0x = state[i*6+0], p0y = state[i*6+1], p0z = state[i*6+2];
        float dx = p0x - cc[0], dy = p0y - cc[1], dz = p0z - cc[2];
        float p1x = dx*Rm[0] + dy*Rm[3] + dz*Rm[6] + bb[0] + cc[0];
        float p1y = dx*Rm[1] + dy*Rm[4] + dz*Rm[7] + bb[1] + cc[1];
        float p1z = dx*Rm[2] + dy*Rm[5] + dz*Rm[8] + bb[2] + cc[2];
        out[i*3+0] = (p1x - p0x) * 60.f;
        out[i*3+1] = (p1y - p0y) * 60.f;
        out[i*3+2] = (p1z - p0z) * 60.f;
    }
}

// ---------------- launch ----------------
extern "C" void kernel_launch(void* const* d_in, const int* in_sizes, int n_in,
                              void* d_out, int out_size)
{
    const float* state = (const float*)d_in[0];
    const float* attr  = (const float*)d_in[1];
    const float* Ra    = (const float*)d_in[2];
    const int*   recv  = (const int*)d_in[3];
    const int*   send  = (const int*)d_in[4];
    const float* pe_w0 = (const float*)d_in[5],  *pe_b0 = (const float*)d_in[6];
    const float* pe_w1 = (const float*)d_in[7],  *pe_b1 = (const float*)d_in[8];
    const float* re_w0 = (const float*)d_in[9],  *re_b0 = (const float*)d_in[10];
    const float* re_w1 = (const float*)d_in[11], *re_b1 = (const float*)d_in[12];
    const float* re_w2 = (const float*)d_in[13], *re_b2 = (const float*)d_in[14];
    const float* rp_w  = (const float*)d_in[15], *rp_b  = (const float*)d_in[16];
    const float* pp_w  = (const float*)d_in[17], *pp_b  = (const float*)d_in[18];
    const float* rg_w0 = (const float*)d_in[19], *rg_b0 = (const float*)d_in[20];
    const float* rg_w1 = (const float*)d_in[21], *rg_b1 = (const float*)d_in[22];
    const float* rg_w2 = (const float*)d_in[23], *rg_b2 = (const float*)d_in[24];
    const float* fl_w0 = (const float*)d_in[25], *fl_b0 = (const float*)d_in[26];
    const float* fl_w1 = (const float*)d_in[27], *fl_b1 = (const float*)d_in[28];
    const float* fl_w2 = (const float*)d_in[29], *fl_b2 = (const float*)d_in[30];
    float* out = (float*)d_out;

    static int smem_set = 0;
    if (!smem_set) {
        cudaFuncSetAttribute(k_edge_fused,   cudaFuncAttributeMaxDynamicSharedMemorySize, FE_SMEM);
        cudaFuncSetAttribute(k_node_prep,    cudaFuncAttributeMaxDynamicSharedMemorySize, ND_SMEM);
        cudaFuncSetAttribute(k_node_step1uv, cudaFuncAttributeMaxDynamicSharedMemorySize, ND_SMEM);
        cudaFuncSetAttribute(k_node_step2,   cudaFuncAttributeMaxDynamicSharedMemorySize, ND_SMEM);
        smem_set = 1;
    }

    void* bp = nullptr;
    cudaGetSymbolAddress(&bp, g_buf);
    float* B     = (float*)bp;
    float* E2    = B + O_E2;      // Z
    float* nodeR = B + O_NODER;   // reused as U
    float* nodeS = B + O_NODES;   // reused as V
    float* peh   = B + O_PEH;
    float* pet   = B + O_PET;
    float* agg   = B + O_AGG;
    float* pooled= B + O_POOL;
    float* cent  = B + O_RIGID;

    const int PG = (NEDGE * 32) / 256;
    const int ZN = (NPART * 128 + 128 + 255) / 256;

    // prep
    k_centroid<<<1, 256>>>(state, cent);
    k_node_pre<<<NPART / NPB, 128>>>(attr, state, pe_w0, pe_b0, re_w0, cent,
                                     peh, nodeR, nodeS);
    k_node_prep<<<FE_GRID, 256, ND_SMEM>>>(peh, pe_w1, pe_b1, pp_w, pp_b, pet);

    // fused edge pipeline: h0 -> re1 -> re2 -> Z (+ step-1 scatter into agg)
    k_zero<<<ZN, 256>>>(agg, NPART * 128 + 128);
    k_edge_fused<<<FE_GRID, 256, FE_SMEM>>>(nodeR, nodeS, Ra, recv, send,
                                            re_w0, re_b0,
                                            re_w1, re_b1, re_w2, re_b2,
                                            rp_w, rp_b, E2, agg);

    // step-1 particle update + U/V (eff never materialized)
    k_node_step1uv<<<FE_GRID, 256, ND_SMEM>>>(agg, pet, pp_w, rp_w, nodeR, nodeS);

    // step-2 propagation
    k_zero<<<ZN, 256>>>(agg, NPART * 128 + 128);     // also zeroes pooled
    k_edge_prop<<<PG, 256>>>(E2, nodeR, nodeS, recv, send, agg);

    // step-2 particle update + rigid pooling + fluid MLP + fluid output
    k_node_step2<<<FE_GRID, 256, ND_SMEM>>>(agg, pet, pp_w,
                                            fl_w0, fl_b0, fl_w1, fl_b1, fl_w2, fl_b2,
                                            pooled, out);

    // rigid predictor
    k_rigid<<<1, 128>>>(state, pooled, rg_w0, rg_b0, rg_w1, rg_b1, rg_w2, rg_b2,
                        cent, out);
}